// round 2
// baseline (speedup 1.0000x reference)
#include <cuda_runtime.h>
#include <math.h>

// Problem constants
#define BB 2
#define LL 2048
#define CC 1024
#define HH 16
#define DD 64
#define MM (BB * LL)          // 4096
#define N_QKV (3 * CC)        // 3072
#define MAX_SM 4.6051701859880913680f  // log(100)

// ---------------------------------------------------------------------------
// Scratch (device globals; no allocations allowed)
// ---------------------------------------------------------------------------
__device__ float g_qkv[MM * N_QKV];          // (B*L, 3C)   50.3 MB
__device__ float g_q[BB * HH * LL * DD];     // (B,H,L,D)   16.8 MB
__device__ float g_k[BB * HH * LL * DD];
__device__ float g_v[BB * HH * LL * DD];
__device__ float g_attn[MM * CC];            // (B,L,C)     16.8 MB

// ---------------------------------------------------------------------------
// SGEMM: C[M x N] = A[M x K] @ B[N x K]^T + bias(n)
// Both A and B are row-major with K contiguous (NT GEMM).
// MODE 0: qkv bias (q_bias | 0 | v_bias).  MODE 1: bias1[n].
// BM=BN=128, BK=16, 256 threads, 8x8 per thread.
// ---------------------------------------------------------------------------
template <int MODE>
__global__ __launch_bounds__(256) void sgemm_nt(
    const float* __restrict__ A, const float* __restrict__ Bm,
    const float* __restrict__ bias1, const float* __restrict__ bias2,
    float* __restrict__ C, int N, int K)
{
    const int BM = 128, BK = 16;
    __shared__ float As[BK][BM + 4];
    __shared__ float Bs[BK][BM + 4];

    const int tid = threadIdx.x;
    const int m0 = blockIdx.y * BM;
    const int n0 = blockIdx.x * BM;

    const int loadRow = tid >> 2;        // 0..63
    const int loadK4  = (tid & 3) * 4;   // 0,4,8,12
    const int rBase = (tid >> 4) * 8;    // 0..120
    const int cBase = (tid & 15) * 8;    // 0..120

    float acc[8][8];
#pragma unroll
    for (int i = 0; i < 8; i++)
#pragma unroll
        for (int j = 0; j < 8; j++) acc[i][j] = 0.f;

    for (int kt = 0; kt < K; kt += BK) {
#pragma unroll
        for (int l = 0; l < 2; l++) {
            int row = loadRow + l * 64;
            float4 a = *(const float4*)(A + (size_t)(m0 + row) * K + kt + loadK4);
            As[loadK4 + 0][row] = a.x;
            As[loadK4 + 1][row] = a.y;
            As[loadK4 + 2][row] = a.z;
            As[loadK4 + 3][row] = a.w;
            float4 b = *(const float4*)(Bm + (size_t)(n0 + row) * K + kt + loadK4);
            Bs[loadK4 + 0][row] = b.x;
            Bs[loadK4 + 1][row] = b.y;
            Bs[loadK4 + 2][row] = b.z;
            Bs[loadK4 + 3][row] = b.w;
        }
        __syncthreads();

#pragma unroll
        for (int k = 0; k < BK; k++) {
            float ra[8], rb[8];
            *(float4*)(ra)     = *(const float4*)&As[k][rBase];
            *(float4*)(ra + 4) = *(const float4*)&As[k][rBase + 4];
            *(float4*)(rb)     = *(const float4*)&Bs[k][cBase];
            *(float4*)(rb + 4) = *(const float4*)&Bs[k][cBase + 4];
#pragma unroll
            for (int i = 0; i < 8; i++)
#pragma unroll
                for (int j = 0; j < 8; j++)
                    acc[i][j] += ra[i] * rb[j];
        }
        __syncthreads();
    }

    float bias[8];
#pragma unroll
    for (int j = 0; j < 8; j++) {
        int c = n0 + cBase + j;
        if (MODE == 0) {
            bias[j] = (c < CC) ? bias1[c] : ((c < 2 * CC) ? 0.f : bias2[c - 2 * CC]);
        } else {
            bias[j] = bias1[c];
        }
    }

#pragma unroll
    for (int i = 0; i < 8; i++) {
        int row = m0 + rBase + i;
        float4 o0, o1;
        o0.x = acc[i][0] + bias[0]; o0.y = acc[i][1] + bias[1];
        o0.z = acc[i][2] + bias[2]; o0.w = acc[i][3] + bias[3];
        o1.x = acc[i][4] + bias[4]; o1.y = acc[i][5] + bias[5];
        o1.z = acc[i][6] + bias[6]; o1.w = acc[i][7] + bias[7];
        *(float4*)(C + (size_t)row * N + n0 + cBase)     = o0;
        *(float4*)(C + (size_t)row * N + n0 + cBase + 4) = o1;
    }
}

// ---------------------------------------------------------------------------
// Normalize + split: one warp per (b, l, h).
// q = l2norm(q) * exp(min(scale_mul[h], log 100)); k = l2norm(k); v copied.
// Output layout (B,H,L,D).
// ---------------------------------------------------------------------------
__global__ __launch_bounds__(256) void norm_split_kernel(
    const float* __restrict__ scale_mul)
{
    int gwarp = (blockIdx.x * 256 + threadIdx.x) >> 5;   // 0 .. 65535
    int lane = threadIdx.x & 31;
    if (gwarp >= BB * LL * HH) return;

    int b = gwarp / (LL * HH);
    int rem = gwarp % (LL * HH);
    int l = rem / HH;
    int h = rem % HH;

    size_t src = (size_t)(b * LL + l) * N_QKV + h * DD;
    size_t dst = ((size_t)(b * HH + h) * LL + l) * DD;

    float sm = __expf(fminf(scale_mul[h], MAX_SM));

    // q
    {
        float v0 = g_qkv[src + lane];
        float v1 = g_qkv[src + 32 + lane];
        float ss = v0 * v0 + v1 * v1;
#pragma unroll
        for (int off = 16; off > 0; off >>= 1)
            ss += __shfl_xor_sync(0xffffffffu, ss, off);
        float inv = 1.0f / fmaxf(sqrtf(ss), 1e-12f);
        g_q[dst + lane]      = v0 * inv * sm;
        g_q[dst + 32 + lane] = v1 * inv * sm;
    }
    // k
    {
        float v0 = g_qkv[src + CC + lane];
        float v1 = g_qkv[src + CC + 32 + lane];
        float ss = v0 * v0 + v1 * v1;
#pragma unroll
        for (int off = 16; off > 0; off >>= 1)
            ss += __shfl_xor_sync(0xffffffffu, ss, off);
        float inv = 1.0f / fmaxf(sqrtf(ss), 1e-12f);
        g_k[dst + lane]      = v0 * inv;
        g_k[dst + 32 + lane] = v1 * inv;
    }
    // v
    {
        g_v[dst + lane]      = g_qkv[src + 2 * CC + lane];
        g_v[dst + 32 + lane] = g_qkv[src + 2 * CC + 32 + lane];
    }
}

// ---------------------------------------------------------------------------
// Flash attention (fp32 SIMT).
// Grid: (L/64 q-tiles, B*H). 256 threads. 64x64 S tiles, online softmax.
// K stored d-major in smem (Kt[d][c]) so hot-loop LDS are conflict-free.
// Output written directly in (B, L, H*D) layout for the projection GEMM.
// ---------------------------------------------------------------------------
#define FLASH_LD 68
#define FLASH_SMEM (4 * 64 * FLASH_LD * 4)  // 69632 bytes

__global__ __launch_bounds__(256) void flash_kernel(
    const float* __restrict__ attn_bias)
{
    extern __shared__ float smem[];
    float (*Qs)[FLASH_LD] = (float(*)[FLASH_LD])(smem);
    float (*Kt)[FLASH_LD] = (float(*)[FLASH_LD])(smem + 64 * FLASH_LD);
    float (*Vs)[FLASH_LD] = (float(*)[FLASH_LD])(smem + 2 * 64 * FLASH_LD);
    float (*Ps)[FLASH_LD] = (float(*)[FLASH_LD])(smem + 3 * 64 * FLASH_LD);

    const int qt = blockIdx.x;          // 0..31
    const int bh = blockIdx.y;          // 0..31
    const int b = bh / HH, h = bh % HH;
    const int tid = threadIdx.x;
    const int ty = tid >> 4, tx = tid & 15;
    const int q0 = qt * 64;
    const int r0 = ty * 4;

    const float* Qh = g_q + (size_t)bh * LL * DD;
    const float* Kh = g_k + (size_t)bh * LL * DD;
    const float* Vh = g_v + (size_t)bh * LL * DD;

    // load Q tile (row-major, d contiguous)
    for (int i = tid; i < 64 * 16; i += 256) {
        int r = i >> 4, c4 = (i & 15) * 4;
        *(float4*)&Qs[r][c4] = *(const float4*)(Qh + (size_t)(q0 + r) * DD + c4);
    }

    float m[4], l[4], O[4][4];
#pragma unroll
    for (int i = 0; i < 4; i++) {
        m[i] = -3.0e38f; l[i] = 0.f;
#pragma unroll
        for (int j = 0; j < 4; j++) O[i][j] = 0.f;
    }

    for (int kt = 0; kt < LL; kt += 64) {
        __syncthreads();  // protect Kt/Vs from previous PV stage
        for (int i = tid; i < 64 * 16; i += 256) {
            int r = i >> 4, c4 = (i & 15) * 4;
            float4 kv = *(const float4*)(Kh + (size_t)(kt + r) * DD + c4);
            Kt[c4 + 0][r] = kv.x;
            Kt[c4 + 1][r] = kv.y;
            Kt[c4 + 2][r] = kv.z;
            Kt[c4 + 3][r] = kv.w;
            *(float4*)&Vs[r][c4] = *(const float4*)(Vh + (size_t)(kt + r) * DD + c4);
        }
        __syncthreads();

        // S = Q @ K^T + bias
        float S[4][4];
#pragma unroll
        for (int i = 0; i < 4; i++) {
            float4 bb = *(const float4*)(attn_bias + (size_t)(q0 + r0 + i) * LL + kt + tx * 4);
            S[i][0] = bb.x; S[i][1] = bb.y; S[i][2] = bb.z; S[i][3] = bb.w;
        }
#pragma unroll
        for (int d0 = 0; d0 < 64; d0 += 4) {
            float4 qv[4], kv[4];
#pragma unroll
            for (int i = 0; i < 4; i++) qv[i] = *(const float4*)&Qs[r0 + i][d0];
#pragma unroll
            for (int dd = 0; dd < 4; dd++) kv[dd] = *(const float4*)&Kt[d0 + dd][tx * 4];
#pragma unroll
            for (int i = 0; i < 4; i++) {
                S[i][0] += qv[i].x * kv[0].x + qv[i].y * kv[1].x + qv[i].z * kv[2].x + qv[i].w * kv[3].x;
                S[i][1] += qv[i].x * kv[0].y + qv[i].y * kv[1].y + qv[i].z * kv[2].y + qv[i].w * kv[3].y;
                S[i][2] += qv[i].x * kv[0].z + qv[i].y * kv[1].z + qv[i].z * kv[2].z + qv[i].w * kv[3].z;
                S[i][3] += qv[i].x * kv[0].w + qv[i].y * kv[1].w + qv[i].z * kv[2].w + qv[i].w * kv[3].w;
            }
        }

        // online softmax (row reductions across the 16-lane tx group)
#pragma unroll
        for (int i = 0; i < 4; i++) {
            float mt = fmaxf(fmaxf(S[i][0], S[i][1]), fmaxf(S[i][2], S[i][3]));
#pragma unroll
            for (int off = 1; off < 16; off <<= 1)
                mt = fmaxf(mt, __shfl_xor_sync(0xffffffffu, mt, off));
            float mn = fmaxf(m[i], mt);
            float alpha = __expf(m[i] - mn);
            float p0 = __expf(S[i][0] - mn);
            float p1 = __expf(S[i][1] - mn);
            float p2 = __expf(S[i][2] - mn);
            float p3 = __expf(S[i][3] - mn);
            float ls = p0 + p1 + p2 + p3;
#pragma unroll
            for (int off = 1; off < 16; off <<= 1)
                ls += __shfl_xor_sync(0xffffffffu, ls, off);
            l[i] = l[i] * alpha + ls;
            m[i] = mn;
#pragma unroll
            for (int j = 0; j < 4; j++) O[i][j] *= alpha;
            float4 pp; pp.x = p0; pp.y = p1; pp.z = p2; pp.w = p3;
            *(float4*)&Ps[r0 + i][tx * 4] = pp;
        }
        __syncthreads();

        // O += P @ V
#pragma unroll
        for (int k0 = 0; k0 < 64; k0 += 4) {
            float4 pv[4], vv[4];
#pragma unroll
            for (int i = 0; i < 4; i++) pv[i] = *(const float4*)&Ps[r0 + i][k0];
#pragma unroll
            for (int kk = 0; kk < 4; kk++) vv[kk] = *(const float4*)&Vs[k0 + kk][tx * 4];
#pragma unroll
            for (int i = 0; i < 4; i++) {
                O[i][0] += pv[i].x * vv[0].x + pv[i].y * vv[1].x + pv[i].z * vv[2].x + pv[i].w * vv[3].x;
                O[i][1] += pv[i].x * vv[0].y + pv[i].y * vv[1].y + pv[i].z * vv[2].y + pv[i].w * vv[3].y;
                O[i][2] += pv[i].x * vv[0].z + pv[i].y * vv[1].z + pv[i].z * vv[2].z + pv[i].w * vv[3].z;
                O[i][3] += pv[i].x * vv[0].w + pv[i].y * vv[1].w + pv[i].z * vv[2].w + pv[i].w * vv[3].w;
            }
        }
    }

    // finalize and write into (B, L, H*D)
#pragma unroll
    for (int i = 0; i < 4; i++) {
        float inv = 1.0f / l[i];
        int row = q0 + r0 + i;
        float4 o;
        o.x = O[i][0] * inv; o.y = O[i][1] * inv;
        o.z = O[i][2] * inv; o.w = O[i][3] * inv;
        *(float4*)(g_attn + (size_t)(b * LL + row) * CC + h * DD + tx * 4) = o;
    }
}

// ---------------------------------------------------------------------------
// launch
// ---------------------------------------------------------------------------
extern "C" void kernel_launch(void* const* d_in, const int* in_sizes, int n_in,
                              void* d_out, int out_size)
{
    const float* x         = (const float*)d_in[0];
    const float* attn_bias = (const float*)d_in[1];
    const float* W_qkv     = (const float*)d_in[2];
    const float* q_bias    = (const float*)d_in[3];
    const float* v_bias    = (const float*)d_in[4];
    const float* scale_mul = (const float*)d_in[5];
    const float* W_proj    = (const float*)d_in[6];
    const float* b_proj    = (const float*)d_in[7];
    float* out = (float*)d_out;

    float* qkv_p = nullptr;
    float* attn_p = nullptr;
    cudaGetSymbolAddress((void**)&qkv_p, g_qkv);
    cudaGetSymbolAddress((void**)&attn_p, g_attn);
    cudaFuncSetAttribute(flash_kernel,
                         cudaFuncAttributeMaxDynamicSharedMemorySize, FLASH_SMEM);

    // 1) QKV projection
    sgemm_nt<0><<<dim3(N_QKV / 128, MM / 128), 256>>>(
        x, W_qkv, q_bias, v_bias, qkv_p, N_QKV, CC);

    // 2) normalize + split
    norm_split_kernel<<<(BB * LL * HH * 32) / 256, 256>>>(scale_mul);

    // 3) attention
    flash_kernel<<<dim3(LL / 64, BB * HH), 256, FLASH_SMEM>>>(attn_bias);

    // 4) output projection
    sgemm_nt<1><<<dim3(CC / 128, MM / 128), 256>>>(
        attn_p, W_proj, b_proj, nullptr, out, CC, CC);
}

// round 5
// speedup vs baseline: 2.0719x; 2.0719x over previous
#include <cuda_runtime.h>
#include <math.h>
#include <stdint.h>

#define BB 2
#define LL 2048
#define CC 1024
#define HH 16
#define DD 64
#define MM (BB * LL)
#define KE 3072
#define DE 192
#define MAX_SM 4.6051701859880913680f

__device__ float    g_qkv[MM * 3 * CC];
__device__ uint16_t g_x3[MM * KE];
__device__ uint16_t g_wq3[3 * CC * KE];
__device__ uint16_t g_wp3[CC * KE];
__device__ uint16_t g_q3[BB * HH * LL * DE];
__device__ uint16_t g_k3[BB * HH * LL * DE];
__device__ uint16_t g_vt3[(size_t)BB * HH * DD * 3 * LL];
__device__ uint16_t g_a3[MM * KE];
__device__ unsigned g_bmax_bits;

__device__ __forceinline__ uint32_t smem_u32(const void* p) {
    uint32_t a;
    asm("{ .reg .u64 t; cvta.to.shared.u64 t, %1; cvt.u32.u64 %0, t; }" : "=r"(a) : "l"(p));
    return a;
}
__device__ __forceinline__ void cp16(uint32_t dst, const void* src) {
    asm volatile("cp.async.cg.shared.global [%0], [%1], 16;" :: "r"(dst), "l"(src));
}
#define CP_COMMIT() asm volatile("cp.async.commit_group;")
#define CP_WAIT0()  asm volatile("cp.async.wait_group 0;" ::: "memory")
#define CP_WAIT1()  asm volatile("cp.async.wait_group 1;" ::: "memory")
#define CP_WAIT2()  asm volatile("cp.async.wait_group 2;" ::: "memory")

__device__ __forceinline__ void ldm4(uint32_t& r0, uint32_t& r1, uint32_t& r2, uint32_t& r3, uint32_t a) {
    asm volatile("ldmatrix.sync.aligned.m8n8.x4.shared.b16 {%0,%1,%2,%3}, [%4];"
                 : "=r"(r0), "=r"(r1), "=r"(r2), "=r"(r3) : "r"(a));
}
__device__ __forceinline__ void mma16816(float* c, uint32_t a0, uint32_t a1, uint32_t a2, uint32_t a3,
                                         uint32_t b0, uint32_t b1) {
    asm volatile("mma.sync.aligned.m16n8k16.row.col.f32.bf16.bf16.f32 "
                 "{%0,%1,%2,%3}, {%4,%5,%6,%7}, {%8,%9}, {%0,%1,%2,%3};"
                 : "+f"(c[0]), "+f"(c[1]), "+f"(c[2]), "+f"(c[3])
                 : "r"(a0), "r"(a1), "r"(a2), "r"(a3), "r"(b0), "r"(b1));
}
__device__ __forceinline__ void st32s(uint32_t a, uint32_t v) {
    asm volatile("st.shared.b32 [%0], %1;" :: "r"(a), "r"(v) : "memory");
}
__device__ __forceinline__ uint32_t pack_bf(float lo, float hi) {
    uint32_t r;
    asm("cvt.rn.bf16x2.f32 %0, %1, %2;" : "=r"(r) : "f"(hi), "f"(lo));
    return r;
}
__device__ __forceinline__ void split2(float a, float b, uint32_t& hi, uint32_t& lo) {
    hi = pack_bf(a, b);
    float ha = __uint_as_float(hi << 16);
    float hb = __uint_as_float(hi & 0xFFFF0000u);
    lo = pack_bf(a - ha, b - hb);
}

// fp32 [rows x 1024] -> bf16 [rows x 3072]. AMODE 1: [hi|hi|lo], 0: [hi|lo|hi]
template <int AMODE>
__global__ __launch_bounds__(256) void split3_kernel(
    const float* __restrict__ in, uint16_t* __restrict__ out, int n4)
{
    int i = blockIdx.x * 256 + threadIdx.x;
    if (i >= n4) return;
    int row = i >> 8, c4 = (i & 255) * 4;
    float4 v = ((const float4*)in)[i];
    uint32_t h01, l01, h23, l23;
    split2(v.x, v.y, h01, l01);
    split2(v.z, v.w, h23, l23);
    uint2 hv; hv.x = h01; hv.y = h23;
    uint2 lv; lv.x = l01; lv.y = l23;
    size_t base = (size_t)row * KE + c4;
    *(uint2*)(out + base) = hv;
    *(uint2*)(out + base + 1024) = AMODE ? hv : lv;
    *(uint2*)(out + base + 2048) = AMODE ? lv : hv;
}

__global__ void bmax_init() { g_bmax_bits = 0; }
__global__ __launch_bounds__(256) void bmax_reduce(const float* __restrict__ b, int n)
{
    float m = 0.f;
    for (int i = blockIdx.x * 256 + threadIdx.x; i < n; i += gridDim.x * 256)
        m = fmaxf(m, fabsf(b[i]));
#pragma unroll
    for (int off = 16; off > 0; off >>= 1)
        m = fmaxf(m, __shfl_xor_sync(0xffffffffu, m, off));
    if ((threadIdx.x & 31) == 0) atomicMax(&g_bmax_bits, __float_as_uint(m));
}

// ---------------- GEMM: C[M x N] = A[M x 3072] @ B[N x 3072]^T + bias ----------------
#define GP 40
#define GSTG 4
#define GEMM_SMEM (GSTG * 2 * 128 * GP * 2)

template <int MODE>
__global__ __launch_bounds__(256) void gemm_bf16(
    const uint16_t* __restrict__ A, const uint16_t* __restrict__ Bm,
    const float* __restrict__ bias1, const float* __restrict__ bias2,
    float* __restrict__ C, int N)
{
    extern __shared__ __align__(16) uint8_t gsm[];
    uint32_t sA = smem_u32(gsm);
    uint32_t sB = sA + GSTG * 128 * GP * 2;
    const int tid = threadIdx.x, w = tid >> 5, lane = tid & 31;
    const int m0 = blockIdx.y * 128, n0 = blockIdx.x * 128;
    const int wr = w >> 2, wc = w & 3;
    const int mw = wr * 64, nw = wc * 32;
    const int g = lane >> 3, r = lane & 7;
    const int tq = lane >> 2, tr = lane & 3;

    float acc[4][4][4];
#pragma unroll
    for (int a = 0; a < 4; a++)
#pragma unroll
        for (int b = 0; b < 4; b++)
#pragma unroll
            for (int c = 0; c < 4; c++) acc[a][b][c] = 0.f;

#define GLOAD(s, kt) do { \
    _Pragma("unroll") \
    for (int t = 0; t < 2; t++) { \
        int j = tid + t * 256; int row = j >> 2, cc = (j & 3) * 8; \
        cp16(sA + (uint32_t)((s) * 128 * GP + row * GP + cc) * 2, A + (size_t)(m0 + row) * KE + (kt) + cc); \
        cp16(sB + (uint32_t)((s) * 128 * GP + row * GP + cc) * 2, Bm + (size_t)(n0 + row) * KE + (kt) + cc); \
    } } while (0)

    const int NK = KE / 32;
#pragma unroll
    for (int p = 0; p < GSTG - 1; p++) { GLOAD(p, p * 32); CP_COMMIT(); }

    for (int it = 0; it < NK; it++) {
        int s = it & (GSTG - 1);
        CP_WAIT2();
        __syncthreads();
        if (it + GSTG - 1 < NK) { GLOAD((it + GSTG - 1) & (GSTG - 1), (it + GSTG - 1) * 32); CP_COMMIT(); }
        uint32_t baseA = sA + (uint32_t)(s * 128 * GP) * 2;
        uint32_t baseB = sB + (uint32_t)(s * 128 * GP) * 2;
#pragma unroll
        for (int ks = 0; ks < 2; ks++) {
            uint32_t af[4][4];
#pragma unroll
            for (int mi = 0; mi < 4; mi++)
                ldm4(af[mi][0], af[mi][1], af[mi][2], af[mi][3],
                     baseA + (uint32_t)((mw + mi * 16 + r + (g & 1) * 8) * GP + ks * 16 + (g >> 1) * 8) * 2);
#pragma unroll
            for (int nj = 0; nj < 2; nj++) {
                uint32_t b0, b1, b2, b3;
                ldm4(b0, b1, b2, b3,
                     baseB + (uint32_t)((nw + nj * 16 + (g >> 1) * 8 + r) * GP + ks * 16 + (g & 1) * 8) * 2);
#pragma unroll
                for (int mi = 0; mi < 4; mi++) {
                    mma16816(acc[mi][nj * 2 + 0], af[mi][0], af[mi][1], af[mi][2], af[mi][3], b0, b1);
                    mma16816(acc[mi][nj * 2 + 1], af[mi][0], af[mi][1], af[mi][2], af[mi][3], b2, b3);
                }
            }
        }
    }
#undef GLOAD

#pragma unroll
    for (int mi = 0; mi < 4; mi++) {
#pragma unroll
        for (int nt = 0; nt < 4; nt++) {
            int colg = n0 + nw + nt * 8 + tr * 2;
            float b0, b1;
            if (MODE == 0) {
                b0 = (colg < CC) ? bias1[colg] : ((colg < 2 * CC) ? 0.f : bias2[colg - 2 * CC]);
                int c1 = colg + 1;
                b1 = (c1 < CC) ? bias1[c1] : ((c1 < 2 * CC) ? 0.f : bias2[c1 - 2 * CC]);
            } else { b0 = bias1[colg]; b1 = bias1[colg + 1]; }
            int rA = m0 + mw + mi * 16 + tq;
            float2 v0, v1;
            v0.x = acc[mi][nt][0] + b0; v0.y = acc[mi][nt][1] + b1;
            v1.x = acc[mi][nt][2] + b0; v1.y = acc[mi][nt][3] + b1;
            *(float2*)(C + (size_t)rA * N + colg) = v0;
            *(float2*)(C + (size_t)(rA + 8) * N + colg) = v1;
        }
    }
}

// ---------------- normalize + split q,k -> (B,H,L,192) ----------------
__global__ __launch_bounds__(256) void norm_split_kernel(const float* __restrict__ scale_mul)
{
    int gwarp = (blockIdx.x * 256 + threadIdx.x) >> 5;
    int lane = threadIdx.x & 31;
    if (gwarp >= BB * LL * HH) return;
    int b = gwarp / (LL * HH), rem = gwarp % (LL * HH);
    int l = rem / HH, h = rem % HH;
    size_t src = (size_t)(b * LL + l) * (3 * CC) + h * DD;
    size_t dst = ((size_t)((b * HH + h) * LL) + l) * DE;
    float sm = __expf(fminf(scale_mul[h], MAX_SM));

    {   // q: [hi|hi|lo] * sm
        float v0 = g_qkv[src + lane], v1 = g_qkv[src + 32 + lane];
        float ss = v0 * v0 + v1 * v1;
#pragma unroll
        for (int off = 16; off > 0; off >>= 1) ss += __shfl_xor_sync(0xffffffffu, ss, off);
        float inv = sm / fmaxf(sqrtf(ss), 1e-12f);
        uint32_t h0, l0, h1, l1;
        split2(v0 * inv, 0.f, h0, l0);
        split2(v1 * inv, 0.f, h1, l1);
        g_q3[dst + lane] = (uint16_t)h0;  g_q3[dst + 64 + lane] = (uint16_t)h0;  g_q3[dst + 128 + lane] = (uint16_t)l0;
        g_q3[dst + 32 + lane] = (uint16_t)h1; g_q3[dst + 96 + lane] = (uint16_t)h1; g_q3[dst + 160 + lane] = (uint16_t)l1;
    }
    {   // k: [hi|lo|hi]
        float v0 = g_qkv[src + CC + lane], v1 = g_qkv[src + CC + 32 + lane];
        float ss = v0 * v0 + v1 * v1;
#pragma unroll
        for (int off = 16; off > 0; off >>= 1) ss += __shfl_xor_sync(0xffffffffu, ss, off);
        float inv = 1.0f / fmaxf(sqrtf(ss), 1e-12f);
        uint32_t h0, l0, h1, l1;
        split2(v0 * inv, 0.f, h0, l0);
        split2(v1 * inv, 0.f, h1, l1);
        g_k3[dst + lane] = (uint16_t)h0;  g_k3[dst + 64 + lane] = (uint16_t)l0;  g_k3[dst + 128 + lane] = (uint16_t)h0;
        g_k3[dst + 32 + lane] = (uint16_t)h1; g_k3[dst + 96 + lane] = (uint16_t)l1; g_k3[dst + 160 + lane] = (uint16_t)h1;
    }
}

// ---------------- V transpose: chunk c -> (B,H,64, c*192 + [hi|lo|hi]) ----------------
__global__ __launch_bounds__(256) void vtrans_kernel()
{
    __shared__ float vt[64][65];
    int tid = threadIdx.x, c = blockIdx.x, bh = blockIdx.y;
    int b = bh >> 4, h = bh & 15;
    int rr = tid >> 2, cs = (tid & 3) * 16;
    const float* src = g_qkv + (size_t)(b * LL + c * 64 + rr) * (3 * CC) + 2 * CC + h * DD + cs;
#pragma unroll
    for (int j4 = 0; j4 < 4; j4++) {
        float4 v = *(const float4*)(src + j4 * 4);
        vt[cs + j4 * 4 + 0][rr] = v.x; vt[cs + j4 * 4 + 1][rr] = v.y;
        vt[cs + j4 * 4 + 2][rr] = v.z; vt[cs + j4 * 4 + 3][rr] = v.w;
    }
    __syncthreads();
    int d = tid >> 2, js = (tid & 3) * 16;
    uint32_t ho[8], lo[8];
#pragma unroll
    for (int j2 = 0; j2 < 8; j2++)
        split2(vt[d][js + j2 * 2], vt[d][js + j2 * 2 + 1], ho[j2], lo[j2]);
    size_t base = ((size_t)(bh * DD + d)) * (3 * LL) + (size_t)c * DE + js;
    *(uint4*)(g_vt3 + base)       = *(uint4*)(ho);
    *(uint4*)(g_vt3 + base + 8)   = *(uint4*)(ho + 4);
    *(uint4*)(g_vt3 + base + 64)  = *(uint4*)(lo);
    *(uint4*)(g_vt3 + base + 72)  = *(uint4*)(lo + 4);
    *(uint4*)(g_vt3 + base + 128) = *(uint4*)(ho);
    *(uint4*)(g_vt3 + base + 136) = *(uint4*)(ho + 4);
}

// ---------------- flash attention via mma.sync ----------------
#define FP 200
#define FQ_OFF 0u
#define FK_OFF 51200u
#define FV_OFF 102400u
#define FPS_OFF 153600u
#define FLR_OFF 204800u
#define FLASH_SMEM 205824

__global__ __launch_bounds__(256) void flash_mma(
    const float* __restrict__ attn_bias, const float* __restrict__ scale_mul)
{
    extern __shared__ __align__(16) uint8_t fsm[];
    uint32_t sb = smem_u32(fsm);
    const int tid = threadIdx.x, w = tid >> 5, lane = tid & 31;
    const int wr = w >> 1, wc = w & 1;
    const int g = lane >> 3, r = lane & 7;
    const int tq = lane >> 2, tr = lane & 3;
    const int q0 = blockIdx.x * 128;
    const int bh = blockIdx.y, b = bh >> 4, h = bh & 15;

    const uint16_t* Qg = g_q3 + ((size_t)bh * LL + q0) * DE;
    const uint16_t* Kg = g_k3 + ((size_t)bh * LL) * DE;
    const uint16_t* Vg = g_vt3 + (size_t)bh * DD * (3 * LL);

#pragma unroll
    for (int t = 0; t < 12; t++) {
        int j = tid + t * 256; int row = j / 24, cc = (j % 24) * 8;
        cp16(sb + FQ_OFF + (uint32_t)(row * FP + cc) * 2, Qg + (size_t)row * DE + cc);
    }
#define LOADKV(cidx, s) do { \
    _Pragma("unroll") \
    for (int t = 0; t < 6; t++) { \
        int j = tid + t * 256; int row = j / 24, cc = (j % 24) * 8; \
        cp16(sb + FK_OFF + (s) * 25600u + (uint32_t)(row * FP + cc) * 2, Kg + (size_t)((cidx) * 64 + row) * DE + cc); \
        cp16(sb + FV_OFF + (s) * 25600u + (uint32_t)(row * FP + cc) * 2, Vg + (size_t)row * (3 * LL) + (size_t)(cidx) * DE + cc); \
    } } while (0)

    LOADKV(0, 0); CP_COMMIT();

    const float M = __expf(fminf(scale_mul[h], MAX_SM)) + __uint_as_float(g_bmax_bits);
    float oacc[2][4][4];
    float lsum[4] = {0.f, 0.f, 0.f, 0.f};
#pragma unroll
    for (int a = 0; a < 2; a++)
#pragma unroll
        for (int c = 0; c < 4; c++)
#pragma unroll
            for (int e = 0; e < 4; e++) oacc[a][c][e] = 0.f;

    for (int c = 0; c < 32; c++) {
        int s = c & 1;
        if (c < 31) { LOADKV(c + 1, s ^ 1); CP_COMMIT(); CP_WAIT1(); }
        else CP_WAIT0();
        __syncthreads();

        float sacc[2][4][4];
#pragma unroll
        for (int a = 0; a < 2; a++)
#pragma unroll
            for (int n = 0; n < 4; n++)
#pragma unroll
                for (int e = 0; e < 4; e++) sacc[a][n][e] = 0.f;

        uint32_t bK = sb + FK_OFF + s * 25600u;
#pragma unroll
        for (int ks = 0; ks < 12; ks++) {
            uint32_t af[2][4];
#pragma unroll
            for (int mi = 0; mi < 2; mi++)
                ldm4(af[mi][0], af[mi][1], af[mi][2], af[mi][3],
                     sb + FQ_OFF + (uint32_t)((wr * 32 + mi * 16 + r + (g & 1) * 8) * FP + ks * 16 + (g >> 1) * 8) * 2);
#pragma unroll
            for (int nj = 0; nj < 2; nj++) {
                uint32_t b0, b1, b2, b3;
                ldm4(b0, b1, b2, b3,
                     bK + (uint32_t)((wc * 32 + nj * 16 + (g >> 1) * 8 + r) * FP + ks * 16 + (g & 1) * 8) * 2);
#pragma unroll
                for (int mi = 0; mi < 2; mi++) {
                    mma16816(sacc[mi][nj * 2 + 0], af[mi][0], af[mi][1], af[mi][2], af[mi][3], b0, b1);
                    mma16816(sacc[mi][nj * 2 + 1], af[mi][0], af[mi][1], af[mi][2], af[mi][3], b2, b3);
                }
            }
        }

        int ktg = c * 64;
#pragma unroll
        for (int mi = 0; mi < 2; mi++) {
            int rA = wr * 32 + mi * 16 + tq;
#pragma unroll
            for (int nt = 0; nt < 4; nt++) {
                int cl = wc * 32 + nt * 8 + tr * 2;
                float2 bb0 = *(const float2*)(attn_bias + (size_t)(q0 + rA) * LL + ktg + cl);
                float2 bb1 = *(const float2*)(attn_bias + (size_t)(q0 + rA + 8) * LL + ktg + cl);
                float p00 = __expf(sacc[mi][nt][0] + bb0.x - M);
                float p01 = __expf(sacc[mi][nt][1] + bb0.y - M);
                float p10 = __expf(sacc[mi][nt][2] + bb1.x - M);
                float p11 = __expf(sacc[mi][nt][3] + bb1.y - M);
                lsum[mi * 2 + 0] += p00 + p01;
                lsum[mi * 2 + 1] += p10 + p11;
                uint32_t hA, lA, hB, lB;
                split2(p00, p01, hA, lA);
                split2(p10, p11, hB, lB);
                uint32_t a0 = sb + FPS_OFF + (uint32_t)(rA * FP + cl) * 2;
                uint32_t a1 = sb + FPS_OFF + (uint32_t)((rA + 8) * FP + cl) * 2;
                st32s(a0, hA); st32s(a0 + 128, hA); st32s(a0 + 256, lA);
                st32s(a1, hB); st32s(a1 + 128, hB); st32s(a1 + 256, lB);
            }
        }
        __syncthreads();

        uint32_t bV = sb + FV_OFF + s * 25600u;
#pragma unroll
        for (int ks = 0; ks < 12; ks++) {
            uint32_t af[2][4];
#pragma unroll
            for (int mi = 0; mi < 2; mi++)
                ldm4(af[mi][0], af[mi][1], af[mi][2], af[mi][3],
                     sb + FPS_OFF + (uint32_t)((wr * 32 + mi * 16 + r + (g & 1) * 8) * FP + ks * 16 + (g >> 1) * 8) * 2);
#pragma unroll
            for (int nj = 0; nj < 2; nj++) {
                uint32_t b0, b1, b2, b3;
                ldm4(b0, b1, b2, b3,
                     bV + (uint32_t)((wc * 32 + nj * 16 + (g >> 1) * 8 + r) * FP + ks * 16 + (g & 1) * 8) * 2);
#pragma unroll
                for (int mi = 0; mi < 2; mi++) {
                    mma16816(oacc[mi][nj * 2 + 0], af[mi][0], af[mi][1], af[mi][2], af[mi][3], b0, b1);
                    mma16816(oacc[mi][nj * 2 + 1], af[mi][0], af[mi][1], af[mi][2], af[mi][3], b2, b3);
                }
            }
        }
        __syncthreads();
    }
#undef LOADKV

    // row-sum reduction: 4 lanes (tr) then across wc via smem
#pragma unroll
    for (int a = 0; a < 4; a++) {
        lsum[a] += __shfl_xor_sync(0xffffffffu, lsum[a], 1);
        lsum[a] += __shfl_xor_sync(0xffffffffu, lsum[a], 2);
    }
    float* lred = (float*)(fsm + FLR_OFF);
    if (tr == 0) {
#pragma unroll
        for (int mi = 0; mi < 2; mi++) {
            lred[(wr * 32 + mi * 16 + tq) * 2 + wc] = lsum[mi * 2];
            lred[(wr * 32 + mi * 16 + tq + 8) * 2 + wc] = lsum[mi * 2 + 1];
        }
    }
    __syncthreads();
#pragma unroll
    for (int mi = 0; mi < 2; mi++) {
        int rA = wr * 32 + mi * 16 + tq;
        float inv0 = 1.f / (lred[rA * 2] + lred[rA * 2 + 1]);
        float inv1 = 1.f / (lred[(rA + 8) * 2] + lred[(rA + 8) * 2 + 1]);
        size_t r0g = (size_t)(b * LL + q0 + rA) * KE + h * DD;
        size_t r1g = (size_t)(b * LL + q0 + rA + 8) * KE + h * DD;
#pragma unroll
        for (int nt = 0; nt < 4; nt++) {
            int cl = wc * 32 + nt * 8 + tr * 2;
            uint32_t hA, lA, hB, lB;
            split2(oacc[mi][nt][0] * inv0, oacc[mi][nt][1] * inv0, hA, lA);
            split2(oacc[mi][nt][2] * inv1, oacc[mi][nt][3] * inv1, hB, lB);
            *(uint32_t*)(g_a3 + r0g + cl) = hA;
            *(uint32_t*)(g_a3 + r0g + 1024 + cl) = hA;
            *(uint32_t*)(g_a3 + r0g + 2048 + cl) = lA;
            *(uint32_t*)(g_a3 + r1g + cl) = hB;
            *(uint32_t*)(g_a3 + r1g + 1024 + cl) = hB;
            *(uint32_t*)(g_a3 + r1g + 2048 + cl) = lB;
        }
    }
}

extern "C" void kernel_launch(void* const* d_in, const int* in_sizes, int n_in,
                              void* d_out, int out_size)
{
    const float* x         = (const float*)d_in[0];
    const float* attn_bias = (const float*)d_in[1];
    const float* W_qkv     = (const float*)d_in[2];
    const float* q_bias    = (const float*)d_in[3];
    const float* v_bias    = (const float*)d_in[4];
    const float* scale_mul = (const float*)d_in[5];
    const float* W_proj    = (const float*)d_in[6];
    const float* b_proj    = (const float*)d_in[7];
    float* out = (float*)d_out;

    float* qkv_p; uint16_t *x3, *wq3, *wp3, *a3;
    cudaGetSymbolAddress((void**)&qkv_p, g_qkv);
    cudaGetSymbolAddress((void**)&x3, g_x3);
    cudaGetSymbolAddress((void**)&wq3, g_wq3);
    cudaGetSymbolAddress((void**)&wp3, g_wp3);
    cudaGetSymbolAddress((void**)&a3, g_a3);

    cudaFuncSetAttribute(gemm_bf16<0>, cudaFuncAttributeMaxDynamicSharedMemorySize, GEMM_SMEM);
    cudaFuncSetAttribute(gemm_bf16<1>, cudaFuncAttributeMaxDynamicSharedMemorySize, GEMM_SMEM);
    cudaFuncSetAttribute(flash_mma, cudaFuncAttributeMaxDynamicSharedMemorySize, FLASH_SMEM);

    split3_kernel<1><<<(MM * CC / 4 + 255) / 256, 256>>>(x, x3, MM * CC / 4);
    split3_kernel<0><<<(3 * CC * CC / 4 + 255) / 256, 256>>>(W_qkv, wq3, 3 * CC * CC / 4);
    split3_kernel<0><<<(CC * CC / 4 + 255) / 256, 256>>>(W_proj, wp3, CC * CC / 4);
    bmax_init<<<1, 1>>>();
    bmax_reduce<<<1024, 256>>>(attn_bias, LL * LL);

    gemm_bf16<0><<<dim3(3 * CC / 128, MM / 128), 256, GEMM_SMEM>>>(
        x3, wq3, q_bias, v_bias, qkv_p, 3 * CC);

    norm_split_kernel<<<(BB * LL * HH * 32) / 256, 256>>>(scale_mul);
    vtrans_kernel<<<dim3(LL / 64, BB * HH), 256>>>();

    flash_mma<<<dim3(LL / 128, BB * HH), 256, FLASH_SMEM>>>(attn_bias, scale_mul);

    gemm_bf16<1><<<dim3(CC / 128, MM / 128), 256, GEMM_SMEM>>>(
        a3, wp3, b_proj, nullptr, out, CC);
}

// round 6
// speedup vs baseline: 2.0879x; 1.0077x over previous
#include <cuda_runtime.h>
#include <math.h>
#include <stdint.h>

#define BB 2
#define LL 2048
#define CC 1024
#define HH 16
#define DD 64
#define MM (BB * LL)
#define KE 3072
#define DE 192
#define MAX_SM 4.6051701859880913680f

__device__ float    g_qkv[MM * 3 * CC];
__device__ uint16_t g_x3[MM * KE];
__device__ uint16_t g_wq3[3 * CC * KE];
__device__ uint16_t g_wp3[CC * KE];
__device__ uint16_t g_q3[BB * HH * LL * DE];
__device__ uint16_t g_k3[BB * HH * LL * DE];
__device__ uint16_t g_vt3[(size_t)BB * HH * DD * 3 * LL];
__device__ uint16_t g_a3[MM * KE];
__device__ unsigned g_bmax_bits;   // zero at module load; atomicMax idempotent per replay

__device__ __forceinline__ uint32_t smem_u32(const void* p) {
    uint32_t a;
    asm("{ .reg .u64 t; cvta.to.shared.u64 t, %1; cvt.u32.u64 %0, t; }" : "=r"(a) : "l"(p));
    return a;
}
__device__ __forceinline__ void cp16(uint32_t dst, const void* src) {
    asm volatile("cp.async.cg.shared.global [%0], [%1], 16;" :: "r"(dst), "l"(src));
}
#define CP_COMMIT() asm volatile("cp.async.commit_group;")
#define CP_WAIT0()  asm volatile("cp.async.wait_group 0;" ::: "memory")
#define CP_WAIT1()  asm volatile("cp.async.wait_group 1;" ::: "memory")

__device__ __forceinline__ void ldm4(uint32_t& r0, uint32_t& r1, uint32_t& r2, uint32_t& r3, uint32_t a) {
    asm volatile("ldmatrix.sync.aligned.m8n8.x4.shared.b16 {%0,%1,%2,%3}, [%4];"
                 : "=r"(r0), "=r"(r1), "=r"(r2), "=r"(r3) : "r"(a));
}
__device__ __forceinline__ void mma16816(float* c, uint32_t a0, uint32_t a1, uint32_t a2, uint32_t a3,
                                         uint32_t b0, uint32_t b1) {
    asm volatile("mma.sync.aligned.m16n8k16.row.col.f32.bf16.bf16.f32 "
                 "{%0,%1,%2,%3}, {%4,%5,%6,%7}, {%8,%9}, {%0,%1,%2,%3};"
                 : "+f"(c[0]), "+f"(c[1]), "+f"(c[2]), "+f"(c[3])
                 : "r"(a0), "r"(a1), "r"(a2), "r"(a3), "r"(b0), "r"(b1));
}
__device__ __forceinline__ void st32s(uint32_t a, uint32_t v) {
    asm volatile("st.shared.b32 [%0], %1;" :: "r"(a), "r"(v) : "memory");
}
__device__ __forceinline__ uint32_t pack_bf(float lo, float hi) {
    uint32_t r;
    asm("cvt.rn.bf16x2.f32 %0, %1, %2;" : "=r"(r) : "f"(hi), "f"(lo));
    return r;
}
__device__ __forceinline__ void split2(float a, float b, uint32_t& hi, uint32_t& lo) {
    hi = pack_bf(a, b);
    float ha = __uint_as_float(hi << 16);
    float hb = __uint_as_float(hi & 0xFFFF0000u);
    lo = pack_bf(a - ha, b - hb);
}

// fp32 [rows x 1024] -> bf16 [rows x 3072]. AMODE 1: [hi|hi|lo], 0: [hi|lo|hi]
template <int AMODE>
__global__ __launch_bounds__(256) void split3_kernel(
    const float* __restrict__ in, uint16_t* __restrict__ out, int n4)
{
    int i = blockIdx.x * 256 + threadIdx.x;
    if (i >= n4) return;
    int row = i >> 8, c4 = (i & 255) * 4;
    float4 v = ((const float4*)in)[i];
    uint32_t h01, l01, h23, l23;
    split2(v.x, v.y, h01, l01);
    split2(v.z, v.w, h23, l23);
    uint2 hv; hv.x = h01; hv.y = h23;
    uint2 lv; lv.x = l01; lv.y = l23;
    size_t base = (size_t)row * KE + c4;
    *(uint2*)(out + base) = hv;
    *(uint2*)(out + base + 1024) = AMODE ? hv : lv;
    *(uint2*)(out + base + 2048) = AMODE ? lv : hv;
}

__global__ __launch_bounds__(256) void bmax_reduce(const float* __restrict__ b, int n)
{
    float m = 0.f;
    for (int i = blockIdx.x * 256 + threadIdx.x; i < n; i += gridDim.x * 256)
        m = fmaxf(m, fabsf(b[i]));
#pragma unroll
    for (int off = 16; off > 0; off >>= 1)
        m = fmaxf(m, __shfl_xor_sync(0xffffffffu, m, off));
    if ((threadIdx.x & 31) == 0) atomicMax(&g_bmax_bits, __float_as_uint(m));
}

// ---------------- GEMM: C[M x N] = A[M x 3072] @ B[N x 3072]^T + bias ----------------
// CTA 128x128, 4 warps (2x2 of 64x64), BK=32, 3-stage cp.async.
#define GP 40
#define GEMM_SMEM (3 * 256 * GP * 2)

template <int MODE>
__global__ __launch_bounds__(128) void gemm_bf16(
    const uint16_t* __restrict__ A, const uint16_t* __restrict__ Bm,
    const float* __restrict__ bias1, const float* __restrict__ bias2,
    float* __restrict__ C, int N)
{
    extern __shared__ __align__(16) uint8_t gsm[];
    uint32_t sA = smem_u32(gsm);
    uint32_t sB = sA + 3 * 128 * GP * 2;
    const int tid = threadIdx.x, w = tid >> 5, lane = tid & 31;
    const int m0 = blockIdx.y * 128, n0 = blockIdx.x * 128;
    const int wr = w >> 1, wc = w & 1;
    const int mw = wr * 64, nw = wc * 64;
    const int g = lane >> 3, r = lane & 7;
    const int tq = lane >> 2, tr = lane & 3;

    float acc[4][8][4];
#pragma unroll
    for (int a = 0; a < 4; a++)
#pragma unroll
        for (int b = 0; b < 8; b++)
#pragma unroll
            for (int c = 0; c < 4; c++) acc[a][b][c] = 0.f;

#define GLOAD(s, kt) do { \
    _Pragma("unroll") \
    for (int t = 0; t < 8; t++) { \
        int j = tid + t * 128; int row = j >> 2, cc = (j & 3) * 8; \
        if (row < 128) \
            cp16(sA + (uint32_t)(((s) * 128 + row) * GP + cc) * 2, A + (size_t)(m0 + row) * KE + (kt) + cc); \
        else \
            cp16(sB + (uint32_t)(((s) * 128 + row - 128) * GP + cc) * 2, Bm + (size_t)(n0 + row - 128) * KE + (kt) + cc); \
    } } while (0)

    const int NK = KE / 32;   // 96
    GLOAD(0, 0); CP_COMMIT();
    GLOAD(1, 32); CP_COMMIT();

    for (int it = 0; it < NK; it++) {
        int s = it % 3;
        CP_WAIT1();
        __syncthreads();
        if (it + 2 < NK) { GLOAD((it + 2) % 3, (it + 2) * 32); CP_COMMIT(); }
        uint32_t baseA = sA + (uint32_t)(s * 128 * GP) * 2;
        uint32_t baseB = sB + (uint32_t)(s * 128 * GP) * 2;
#pragma unroll
        for (int ks = 0; ks < 2; ks++) {
            uint32_t af[4][4];
#pragma unroll
            for (int mi = 0; mi < 4; mi++)
                ldm4(af[mi][0], af[mi][1], af[mi][2], af[mi][3],
                     baseA + (uint32_t)((mw + mi * 16 + r + (g & 1) * 8) * GP + ks * 16 + (g >> 1) * 8) * 2);
#pragma unroll
            for (int nj = 0; nj < 4; nj++) {
                uint32_t b0, b1, b2, b3;
                ldm4(b0, b1, b2, b3,
                     baseB + (uint32_t)((nw + nj * 16 + (g >> 1) * 8 + r) * GP + ks * 16 + (g & 1) * 8) * 2);
#pragma unroll
                for (int mi = 0; mi < 4; mi++) {
                    mma16816(acc[mi][nj * 2 + 0], af[mi][0], af[mi][1], af[mi][2], af[mi][3], b0, b1);
                    mma16816(acc[mi][nj * 2 + 1], af[mi][0], af[mi][1], af[mi][2], af[mi][3], b2, b3);
                }
            }
        }
    }
#undef GLOAD

#pragma unroll
    for (int mi = 0; mi < 4; mi++) {
#pragma unroll
        for (int nt = 0; nt < 8; nt++) {
            int colg = n0 + nw + nt * 8 + tr * 2;
            float b0, b1;
            if (MODE == 0) {
                b0 = (colg < CC) ? bias1[colg] : ((colg < 2 * CC) ? 0.f : bias2[colg - 2 * CC]);
                int c1 = colg + 1;
                b1 = (c1 < CC) ? bias1[c1] : ((c1 < 2 * CC) ? 0.f : bias2[c1 - 2 * CC]);
            } else { b0 = bias1[colg]; b1 = bias1[colg + 1]; }
            int rA = m0 + mw + mi * 16 + tq;
            float2 v0, v1;
            v0.x = acc[mi][nt][0] + b0; v0.y = acc[mi][nt][1] + b1;
            v1.x = acc[mi][nt][2] + b0; v1.y = acc[mi][nt][3] + b1;
            *(float2*)(C + (size_t)rA * N + colg) = v0;
            *(float2*)(C + (size_t)(rA + 8) * N + colg) = v1;
        }
    }
}

// ---------------- normalize + split q,k -> (B,H,L,192) ----------------
__global__ __launch_bounds__(256) void norm_split_kernel(const float* __restrict__ scale_mul)
{
    int gwarp = (blockIdx.x * 256 + threadIdx.x) >> 5;
    int lane = threadIdx.x & 31;
    if (gwarp >= BB * LL * HH) return;
    int b = gwarp / (LL * HH), rem = gwarp % (LL * HH);
    int l = rem / HH, h = rem % HH;
    size_t src = (size_t)(b * LL + l) * (3 * CC) + h * DD;
    size_t dst = ((size_t)((b * HH + h) * LL) + l) * DE;
    float sm = __expf(fminf(scale_mul[h], MAX_SM));

    {   // q: [hi|hi|lo] * sm
        float v0 = g_qkv[src + lane], v1 = g_qkv[src + 32 + lane];
        float ss = v0 * v0 + v1 * v1;
#pragma unroll
        for (int off = 16; off > 0; off >>= 1) ss += __shfl_xor_sync(0xffffffffu, ss, off);
        float inv = sm / fmaxf(sqrtf(ss), 1e-12f);
        uint32_t h0, l0, h1, l1;
        split2(v0 * inv, 0.f, h0, l0);
        split2(v1 * inv, 0.f, h1, l1);
        g_q3[dst + lane] = (uint16_t)h0;  g_q3[dst + 64 + lane] = (uint16_t)h0;  g_q3[dst + 128 + lane] = (uint16_t)l0;
        g_q3[dst + 32 + lane] = (uint16_t)h1; g_q3[dst + 96 + lane] = (uint16_t)h1; g_q3[dst + 160 + lane] = (uint16_t)l1;
    }
    {   // k: [hi|lo|hi]
        float v0 = g_qkv[src + CC + lane], v1 = g_qkv[src + CC + 32 + lane];
        float ss = v0 * v0 + v1 * v1;
#pragma unroll
        for (int off = 16; off > 0; off >>= 1) ss += __shfl_xor_sync(0xffffffffu, ss, off);
        float inv = 1.0f / fmaxf(sqrtf(ss), 1e-12f);
        uint32_t h0, l0, h1, l1;
        split2(v0 * inv, 0.f, h0, l0);
        split2(v1 * inv, 0.f, h1, l1);
        g_k3[dst + lane] = (uint16_t)h0;  g_k3[dst + 64 + lane] = (uint16_t)l0;  g_k3[dst + 128 + lane] = (uint16_t)h0;
        g_k3[dst + 32 + lane] = (uint16_t)h1; g_k3[dst + 96 + lane] = (uint16_t)l1; g_k3[dst + 160 + lane] = (uint16_t)h1;
    }
}

// ---------------- V transpose: chunk c -> (B,H,64, c*192 + [hi|lo|hi]) ----------------
__global__ __launch_bounds__(256) void vtrans_kernel()
{
    __shared__ float vt[64][65];
    int tid = threadIdx.x, c = blockIdx.x, bh = blockIdx.y;
    int b = bh >> 4, h = bh & 15;
    int rr = tid >> 2, cs = (tid & 3) * 16;
    const float* src = g_qkv + (size_t)(b * LL + c * 64 + rr) * (3 * CC) + 2 * CC + h * DD + cs;
#pragma unroll
    for (int j4 = 0; j4 < 4; j4++) {
        float4 v = *(const float4*)(src + j4 * 4);
        vt[cs + j4 * 4 + 0][rr] = v.x; vt[cs + j4 * 4 + 1][rr] = v.y;
        vt[cs + j4 * 4 + 2][rr] = v.z; vt[cs + j4 * 4 + 3][rr] = v.w;
    }
    __syncthreads();
    int d = tid >> 2, js = (tid & 3) * 16;
    uint32_t ho[8], lo[8];
#pragma unroll
    for (int j2 = 0; j2 < 8; j2++)
        split2(vt[d][js + j2 * 2], vt[d][js + j2 * 2 + 1], ho[j2], lo[j2]);
    size_t base = ((size_t)(bh * DD + d)) * (3 * LL) + (size_t)c * DE + js;
    *(uint4*)(g_vt3 + base)       = *(uint4*)(ho);
    *(uint4*)(g_vt3 + base + 8)   = *(uint4*)(ho + 4);
    *(uint4*)(g_vt3 + base + 64)  = *(uint4*)(lo);
    *(uint4*)(g_vt3 + base + 72)  = *(uint4*)(lo + 4);
    *(uint4*)(g_vt3 + base + 128) = *(uint4*)(ho);
    *(uint4*)(g_vt3 + base + 136) = *(uint4*)(ho + 4);
}

// ---------------- flash attention via mma.sync ----------------
#define FP 200
#define FQ_OFF 0u
#define FK_OFF 51200u
#define FV_OFF 102400u
#define FPS_OFF 153600u
#define FLR_OFF 204800u
#define FLASH_SMEM 205824

__global__ __launch_bounds__(256) void flash_mma(
    const float* __restrict__ attn_bias, const float* __restrict__ scale_mul)
{
    extern __shared__ __align__(16) uint8_t fsm[];
    uint32_t sb = smem_u32(fsm);
    const int tid = threadIdx.x, w = tid >> 5, lane = tid & 31;
    const int wr = w >> 1, wc = w & 1;
    const int g = lane >> 3, r = lane & 7;
    const int tq = lane >> 2, tr = lane & 3;
    const int q0 = blockIdx.x * 128;
    const int bh = blockIdx.y, b = bh >> 4, h = bh & 15;

    const uint16_t* Qg = g_q3 + ((size_t)bh * LL + q0) * DE;
    const uint16_t* Kg = g_k3 + ((size_t)bh * LL) * DE;
    const uint16_t* Vg = g_vt3 + (size_t)bh * DD * (3 * LL);

#pragma unroll
    for (int t = 0; t < 12; t++) {
        int j = tid + t * 256; int row = j / 24, cc = (j % 24) * 8;
        cp16(sb + FQ_OFF + (uint32_t)(row * FP + cc) * 2, Qg + (size_t)row * DE + cc);
    }
#define LOADKV(cidx, s) do { \
    _Pragma("unroll") \
    for (int t = 0; t < 6; t++) { \
        int j = tid + t * 256; int row = j / 24, cc = (j % 24) * 8; \
        cp16(sb + FK_OFF + (s) * 25600u + (uint32_t)(row * FP + cc) * 2, Kg + (size_t)((cidx) * 64 + row) * DE + cc); \
        cp16(sb + FV_OFF + (s) * 25600u + (uint32_t)(row * FP + cc) * 2, Vg + (size_t)row * (3 * LL) + (size_t)(cidx) * DE + cc); \
    } } while (0)

    LOADKV(0, 0); CP_COMMIT();

    const float M = __expf(fminf(scale_mul[h], MAX_SM)) + __uint_as_float(g_bmax_bits);
    float oacc[2][4][4];
    float lsum[4] = {0.f, 0.f, 0.f, 0.f};
#pragma unroll
    for (int a = 0; a < 2; a++)
#pragma unroll
        for (int c = 0; c < 4; c++)
#pragma unroll
            for (int e = 0; e < 4; e++) oacc[a][c][e] = 0.f;

    for (int c = 0; c < 32; c++) {
        int s = c & 1;
        if (c < 31) { LOADKV(c + 1, s ^ 1); CP_COMMIT(); CP_WAIT1(); }
        else CP_WAIT0();
        __syncthreads();

        // prefetch bias for this chunk (latency hidden behind the QK mma loop)
        int ktg = c * 64;
        float2 bb[2][4][2];
#pragma unroll
        for (int mi = 0; mi < 2; mi++) {
            int rA = wr * 32 + mi * 16 + tq;
#pragma unroll
            for (int nt = 0; nt < 4; nt++) {
                int cl = wc * 32 + nt * 8 + tr * 2;
                bb[mi][nt][0] = *(const float2*)(attn_bias + (size_t)(q0 + rA) * LL + ktg + cl);
                bb[mi][nt][1] = *(const float2*)(attn_bias + (size_t)(q0 + rA + 8) * LL + ktg + cl);
            }
        }

        float sacc[2][4][4];
#pragma unroll
        for (int a = 0; a < 2; a++)
#pragma unroll
            for (int n = 0; n < 4; n++)
#pragma unroll
                for (int e = 0; e < 4; e++) sacc[a][n][e] = 0.f;

        uint32_t bK = sb + FK_OFF + s * 25600u;
#pragma unroll
        for (int ks = 0; ks < 12; ks++) {
            uint32_t af[2][4];
#pragma unroll
            for (int mi = 0; mi < 2; mi++)
                ldm4(af[mi][0], af[mi][1], af[mi][2], af[mi][3],
                     sb + FQ_OFF + (uint32_t)((wr * 32 + mi * 16 + r + (g & 1) * 8) * FP + ks * 16 + (g >> 1) * 8) * 2);
#pragma unroll
            for (int nj = 0; nj < 2; nj++) {
                uint32_t b0, b1, b2, b3;
                ldm4(b0, b1, b2, b3,
                     bK + (uint32_t)((wc * 32 + nj * 16 + (g >> 1) * 8 + r) * FP + ks * 16 + (g & 1) * 8) * 2);
#pragma unroll
                for (int mi = 0; mi < 2; mi++) {
                    mma16816(sacc[mi][nj * 2 + 0], af[mi][0], af[mi][1], af[mi][2], af[mi][3], b0, b1);
                    mma16816(sacc[mi][nj * 2 + 1], af[mi][0], af[mi][1], af[mi][2], af[mi][3], b2, b3);
                }
            }
        }

#pragma unroll
        for (int mi = 0; mi < 2; mi++) {
            int rA = wr * 32 + mi * 16 + tq;
#pragma unroll
            for (int nt = 0; nt < 4; nt++) {
                int cl = wc * 32 + nt * 8 + tr * 2;
                float p00 = __expf(sacc[mi][nt][0] + bb[mi][nt][0].x - M);
                float p01 = __expf(sacc[mi][nt][1] + bb[mi][nt][0].y - M);
                float p10 = __expf(sacc[mi][nt][2] + bb[mi][nt][1].x - M);
                float p11 = __expf(sacc[mi][nt][3] + bb[mi][nt][1].y - M);
                lsum[mi * 2 + 0] += p00 + p01;
                lsum[mi * 2 + 1] += p10 + p11;
                uint32_t hA, lA, hB, lB;
                split2(p00, p01, hA, lA);
                split2(p10, p11, hB, lB);
                uint32_t a0 = sb + FPS_OFF + (uint32_t)(rA * FP + cl) * 2;
                uint32_t a1 = sb + FPS_OFF + (uint32_t)((rA + 8) * FP + cl) * 2;
                st32s(a0, hA); st32s(a0 + 128, hA); st32s(a0 + 256, lA);
                st32s(a1, hB); st32s(a1 + 128, hB); st32s(a1 + 256, lB);
            }
        }
        __syncthreads();

        uint32_t bV = sb + FV_OFF + s * 25600u;
#pragma unroll
        for (int ks = 0; ks < 12; ks++) {
            uint32_t af[2][4];
#pragma unroll
            for (int mi = 0; mi < 2; mi++)
                ldm4(af[mi][0], af[mi][1], af[mi][2], af[mi][3],
                     sb + FPS_OFF + (uint32_t)((wr * 32 + mi * 16 + r + (g & 1) * 8) * FP + ks * 16 + (g >> 1) * 8) * 2);
#pragma unroll
            for (int nj = 0; nj < 2; nj++) {
                uint32_t b0, b1, b2, b3;
                ldm4(b0, b1, b2, b3,
                     bV + (uint32_t)((wc * 32 + nj * 16 + (g >> 1) * 8 + r) * FP + ks * 16 + (g & 1) * 8) * 2);
#pragma unroll
                for (int mi = 0; mi < 2; mi++) {
                    mma16816(oacc[mi][nj * 2 + 0], af[mi][0], af[mi][1], af[mi][2], af[mi][3], b0, b1);
                    mma16816(oacc[mi][nj * 2 + 1], af[mi][0], af[mi][1], af[mi][2], af[mi][3], b2, b3);
                }
            }
        }
        __syncthreads();
    }
#undef LOADKV

#pragma unroll
    for (int a = 0; a < 4; a++) {
        lsum[a] += __shfl_xor_sync(0xffffffffu, lsum[a], 1);
        lsum[a] += __shfl_xor_sync(0xffffffffu, lsum[a], 2);
    }
    float* lred = (float*)(fsm + FLR_OFF);
    if (tr == 0) {
#pragma unroll
        for (int mi = 0; mi < 2; mi++) {
            lred[(wr * 32 + mi * 16 + tq) * 2 + wc] = lsum[mi * 2];
            lred[(wr * 32 + mi * 16 + tq + 8) * 2 + wc] = lsum[mi * 2 + 1];
        }
    }
    __syncthreads();
#pragma unroll
    for (int mi = 0; mi < 2; mi++) {
        int rA = wr * 32 + mi * 16 + tq;
        float inv0 = 1.f / (lred[rA * 2] + lred[rA * 2 + 1]);
        float inv1 = 1.f / (lred[(rA + 8) * 2] + lred[(rA + 8) * 2 + 1]);
        size_t r0g = (size_t)(b * LL + q0 + rA) * KE + h * DD;
        size_t r1g = (size_t)(b * LL + q0 + rA + 8) * KE + h * DD;
#pragma unroll
        for (int nt = 0; nt < 4; nt++) {
            int cl = wc * 32 + nt * 8 + tr * 2;
            uint32_t hA, lA, hB, lB;
            split2(oacc[mi][nt][0] * inv0, oacc[mi][nt][1] * inv0, hA, lA);
            split2(oacc[mi][nt][2] * inv1, oacc[mi][nt][3] * inv1, hB, lB);
            *(uint32_t*)(g_a3 + r0g + cl) = hA;
            *(uint32_t*)(g_a3 + r0g + 1024 + cl) = hA;
            *(uint32_t*)(g_a3 + r0g + 2048 + cl) = lA;
            *(uint32_t*)(g_a3 + r1g + cl) = hB;
            *(uint32_t*)(g_a3 + r1g + 1024 + cl) = hB;
            *(uint32_t*)(g_a3 + r1g + 2048 + cl) = lB;
        }
    }
}

extern "C" void kernel_launch(void* const* d_in, const int* in_sizes, int n_in,
                              void* d_out, int out_size)
{
    const float* x         = (const float*)d_in[0];
    const float* attn_bias = (const float*)d_in[1];
    const float* W_qkv     = (const float*)d_in[2];
    const float* q_bias    = (const float*)d_in[3];
    const float* v_bias    = (const float*)d_in[4];
    const float* scale_mul = (const float*)d_in[5];
    const float* W_proj    = (const float*)d_in[6];
    const float* b_proj    = (const float*)d_in[7];
    float* out = (float*)d_out;

    float* qkv_p; uint16_t *x3, *wq3, *wp3, *a3;
    cudaGetSymbolAddress((void**)&qkv_p, g_qkv);
    cudaGetSymbolAddress((void**)&x3, g_x3);
    cudaGetSymbolAddress((void**)&wq3, g_wq3);
    cudaGetSymbolAddress((void**)&wp3, g_wp3);
    cudaGetSymbolAddress((void**)&a3, g_a3);

    cudaFuncSetAttribute(gemm_bf16<0>, cudaFuncAttributeMaxDynamicSharedMemorySize, GEMM_SMEM);
    cudaFuncSetAttribute(gemm_bf16<1>, cudaFuncAttributeMaxDynamicSharedMemorySize, GEMM_SMEM);
    cudaFuncSetAttribute(flash_mma, cudaFuncAttributeMaxDynamicSharedMemorySize, FLASH_SMEM);

    split3_kernel<1><<<(MM * CC / 4 + 255) / 256, 256>>>(x, x3, MM * CC / 4);
    split3_kernel<0><<<(3 * CC * CC / 4 + 255) / 256, 256>>>(W_qkv, wq3, 3 * CC * CC / 4);
    split3_kernel<0><<<(CC * CC / 4 + 255) / 256, 256>>>(W_proj, wp3, CC * CC / 4);
    bmax_reduce<<<1024, 256>>>(attn_bias, LL * LL);

    gemm_bf16<0><<<dim3(3 * CC / 128, MM / 128), 128, GEMM_SMEM>>>(
        x3, wq3, q_bias, v_bias, qkv_p, 3 * CC);

    norm_split_kernel<<<(BB * LL * HH * 32) / 256, 256>>>(scale_mul);
    vtrans_kernel<<<dim3(LL / 64, BB * HH), 256>>>();

    flash_mma<<<dim3(LL / 128, BB * HH), 256, FLASH_SMEM>>>(attn_bias, scale_mul);

    gemm_bf16<1><<<dim3(CC / 128, MM / 128), 128, GEMM_SMEM>>>(
        a3, wp3, b_proj, nullptr, out, CC);
}

// round 7
// speedup vs baseline: 2.3945x; 1.1469x over previous
#include <cuda_runtime.h>
#include <math.h>
#include <stdint.h>

#define BB 2
#define LL 2048
#define CC 1024
#define HH 16
#define DD 64
#define MM (BB * LL)
#define KE 3072
#define MAX_SM 4.6051701859880913680f

__device__ float    g_qkv[MM * 3 * CC];
__device__ uint16_t g_xh[MM * CC],  g_xl[MM * CC];
__device__ uint16_t g_wqh[3 * CC * CC], g_wql[3 * CC * CC];
__device__ uint16_t g_wph[CC * CC], g_wpl[CC * CC];
__device__ uint16_t g_q2[BB * HH * LL * 128];              // [qhi(64)|qlo(64)]
__device__ uint16_t g_k2[BB * HH * LL * 128];              // [khi|klo]
__device__ uint16_t g_vt2[(size_t)BB * HH * DD * 2 * LL];  // row d, chunk c: [vhi|vlo]
__device__ uint16_t g_ah[MM * CC], g_al[MM * CC];
__device__ unsigned g_bmax_bits;   // zero at load; atomicMax idempotent per replay

__device__ __forceinline__ uint32_t smem_u32(const void* p) {
    uint32_t a;
    asm("{ .reg .u64 t; cvta.to.shared.u64 t, %1; cvt.u32.u64 %0, t; }" : "=r"(a) : "l"(p));
    return a;
}
__device__ __forceinline__ void cp16(uint32_t dst, const void* src) {
    asm volatile("cp.async.cg.shared.global [%0], [%1], 16;" :: "r"(dst), "l"(src));
}
#define CP_COMMIT() asm volatile("cp.async.commit_group;")
#define CP_WAIT0()  asm volatile("cp.async.wait_group 0;" ::: "memory")
#define CP_WAIT1()  asm volatile("cp.async.wait_group 1;" ::: "memory")

__device__ __forceinline__ void ldm4(uint32_t& r0, uint32_t& r1, uint32_t& r2, uint32_t& r3, uint32_t a) {
    asm volatile("ldmatrix.sync.aligned.m8n8.x4.shared.b16 {%0,%1,%2,%3}, [%4];"
                 : "=r"(r0), "=r"(r1), "=r"(r2), "=r"(r3) : "r"(a));
}
__device__ __forceinline__ void mma16816(float* c, uint32_t a0, uint32_t a1, uint32_t a2, uint32_t a3,
                                         uint32_t b0, uint32_t b1) {
    asm volatile("mma.sync.aligned.m16n8k16.row.col.f32.bf16.bf16.f32 "
                 "{%0,%1,%2,%3}, {%4,%5,%6,%7}, {%8,%9}, {%0,%1,%2,%3};"
                 : "+f"(c[0]), "+f"(c[1]), "+f"(c[2]), "+f"(c[3])
                 : "r"(a0), "r"(a1), "r"(a2), "r"(a3), "r"(b0), "r"(b1));
}
__device__ __forceinline__ void st32s(uint32_t a, uint32_t v) {
    asm volatile("st.shared.b32 [%0], %1;" :: "r"(a), "r"(v) : "memory");
}
__device__ __forceinline__ uint32_t pack_bf(float lo, float hi) {
    uint32_t r;
    asm("cvt.rn.bf16x2.f32 %0, %1, %2;" : "=r"(r) : "f"(hi), "f"(lo));
    return r;
}
__device__ __forceinline__ void split2(float a, float b, uint32_t& hi, uint32_t& lo) {
    hi = pack_bf(a, b);
    float ha = __uint_as_float(hi << 16);
    float hb = __uint_as_float(hi & 0xFFFF0000u);
    lo = pack_bf(a - ha, b - hb);
}

// plain split: fp32 -> bf16 hi/lo
__global__ __launch_bounds__(256) void split_kernel(
    const float* __restrict__ in, uint16_t* __restrict__ hi,
    uint16_t* __restrict__ lo, int n4)
{
    int i = blockIdx.x * 256 + threadIdx.x;
    if (i >= n4) return;
    float4 v = ((const float4*)in)[i];
    uint32_t h01, l01, h23, l23;
    split2(v.x, v.y, h01, l01);
    split2(v.z, v.w, h23, l23);
    uint2 hv; hv.x = h01; hv.y = h23;
    uint2 lv; lv.x = l01; lv.y = l23;
    ((uint2*)hi)[i] = hv;
    ((uint2*)lo)[i] = lv;
}

__global__ __launch_bounds__(256) void bmax_reduce(const float* __restrict__ b, int n4)
{
    float m = 0.f;
    for (int i = blockIdx.x * 256 + threadIdx.x; i < n4; i += gridDim.x * 256) {
        float4 v = ((const float4*)b)[i];
        m = fmaxf(m, fmaxf(fmaxf(fabsf(v.x), fabsf(v.y)), fmaxf(fabsf(v.z), fabsf(v.w))));
    }
#pragma unroll
    for (int off = 16; off > 0; off >>= 1)
        m = fmaxf(m, __shfl_xor_sync(0xffffffffu, m, off));
    if ((threadIdx.x & 31) == 0) atomicMax(&g_bmax_bits, __float_as_uint(m));
}

// ---------------- GEMM: C = (Ahi+Alo)(Bhi+Blo)^T via 3-term map over kt=3072 ----------------
// CTA 128x128, 4 warps (64x64 each), BK=32, 3-stage cp.async.
#define GP 40
#define GEMM_SMEM (3 * 256 * GP * 2)

template <int MODE>
__global__ __launch_bounds__(128) void gemm_bf16(
    const uint16_t* __restrict__ Ahi, const uint16_t* __restrict__ Alo,
    const uint16_t* __restrict__ Bhi, const uint16_t* __restrict__ Blo,
    const float* __restrict__ bias1, const float* __restrict__ bias2,
    float* __restrict__ C, int N)
{
    extern __shared__ __align__(16) uint8_t gsm[];
    uint32_t sA = smem_u32(gsm);
    uint32_t sB = sA + 3 * 128 * GP * 2;
    const int tid = threadIdx.x, w = tid >> 5, lane = tid & 31;
    const int m0 = blockIdx.y * 128, n0 = blockIdx.x * 128;
    const int wr = w >> 1, wc = w & 1;
    const int mw = wr * 64, nw = wc * 64;
    const int g = lane >> 3, r = lane & 7;
    const int tq = lane >> 2, tr = lane & 3;

    float acc[4][8][4];
#pragma unroll
    for (int a = 0; a < 4; a++)
#pragma unroll
        for (int b = 0; b < 8; b++)
#pragma unroll
            for (int c = 0; c < 4; c++) acc[a][b][c] = 0.f;

#define GLOAD(s, kt) do { \
    const uint16_t* PA = ((kt) < 2048) ? Ahi : Alo; \
    const uint16_t* PB = ((kt) < 1024 || (kt) >= 2048) ? Bhi : Blo; \
    int ka = ((kt) < 2048) ? ((kt) & 1023) : ((kt) - 2048); \
    int kb = (kt) & 1023; \
    _Pragma("unroll") \
    for (int t = 0; t < 8; t++) { \
        int j = tid + t * 128; int row = j >> 2, cc = (j & 3) * 8; \
        if (row < 128) \
            cp16(sA + (uint32_t)(((s) * 128 + row) * GP + cc) * 2, PA + (size_t)(m0 + row) * 1024 + ka + cc); \
        else \
            cp16(sB + (uint32_t)(((s) * 128 + row - 128) * GP + cc) * 2, PB + (size_t)(n0 + row - 128) * 1024 + kb + cc); \
    } } while (0)

    const int NK = KE / 32;   // 96
    GLOAD(0, 0); CP_COMMIT();
    GLOAD(1, 32); CP_COMMIT();

    for (int it = 0; it < NK; it++) {
        int s = it % 3;
        CP_WAIT1();
        __syncthreads();
        if (it + 2 < NK) { GLOAD((it + 2) % 3, (it + 2) * 32); CP_COMMIT(); }
        uint32_t baseA = sA + (uint32_t)(s * 128 * GP) * 2;
        uint32_t baseB = sB + (uint32_t)(s * 128 * GP) * 2;
#pragma unroll
        for (int ks = 0; ks < 2; ks++) {
            uint32_t af[4][4];
#pragma unroll
            for (int mi = 0; mi < 4; mi++)
                ldm4(af[mi][0], af[mi][1], af[mi][2], af[mi][3],
                     baseA + (uint32_t)((mw + mi * 16 + r + (g & 1) * 8) * GP + ks * 16 + (g >> 1) * 8) * 2);
#pragma unroll
            for (int nj = 0; nj < 4; nj++) {
                uint32_t b0, b1, b2, b3;
                ldm4(b0, b1, b2, b3,
                     baseB + (uint32_t)((nw + nj * 16 + (g >> 1) * 8 + r) * GP + ks * 16 + (g & 1) * 8) * 2);
#pragma unroll
                for (int mi = 0; mi < 4; mi++) {
                    mma16816(acc[mi][nj * 2 + 0], af[mi][0], af[mi][1], af[mi][2], af[mi][3], b0, b1);
                    mma16816(acc[mi][nj * 2 + 1], af[mi][0], af[mi][1], af[mi][2], af[mi][3], b2, b3);
                }
            }
        }
    }
#undef GLOAD

#pragma unroll
    for (int mi = 0; mi < 4; mi++) {
#pragma unroll
        for (int nt = 0; nt < 8; nt++) {
            int colg = n0 + nw + nt * 8 + tr * 2;
            float b0, b1;
            if (MODE == 0) {
                b0 = (colg < CC) ? bias1[colg] : ((colg < 2 * CC) ? 0.f : bias2[colg - 2 * CC]);
                int c1 = colg + 1;
                b1 = (c1 < CC) ? bias1[c1] : ((c1 < 2 * CC) ? 0.f : bias2[c1 - 2 * CC]);
            } else { b0 = bias1[colg]; b1 = bias1[colg + 1]; }
            int rA = m0 + mw + mi * 16 + tq;
            float2 v0, v1;
            v0.x = acc[mi][nt][0] + b0; v0.y = acc[mi][nt][1] + b1;
            v1.x = acc[mi][nt][2] + b0; v1.y = acc[mi][nt][3] + b1;
            *(float2*)(C + (size_t)rA * N + colg) = v0;
            *(float2*)(C + (size_t)(rA + 8) * N + colg) = v1;
        }
    }
}

// ---------------- normalize + split q,k -> (B,H,L,[hi64|lo64]) ----------------
__global__ __launch_bounds__(256) void norm_split_kernel(const float* __restrict__ scale_mul)
{
    int gwarp = (blockIdx.x * 256 + threadIdx.x) >> 5;
    int lane = threadIdx.x & 31;
    if (gwarp >= BB * LL * HH) return;
    int b = gwarp / (LL * HH), rem = gwarp % (LL * HH);
    int l = rem / HH, h = rem % HH;
    size_t src = (size_t)(b * LL + l) * (3 * CC) + h * DD;
    size_t dst = ((size_t)((b * HH + h) * LL) + l) * 128;
    float sm = __expf(fminf(scale_mul[h], MAX_SM));

    {   // q * sm
        float v0 = g_qkv[src + lane], v1 = g_qkv[src + 32 + lane];
        float ss = v0 * v0 + v1 * v1;
#pragma unroll
        for (int off = 16; off > 0; off >>= 1) ss += __shfl_xor_sync(0xffffffffu, ss, off);
        float inv = sm / fmaxf(sqrtf(ss), 1e-12f);
        uint32_t h0, l0, h1, l1;
        split2(v0 * inv, 0.f, h0, l0);
        split2(v1 * inv, 0.f, h1, l1);
        g_q2[dst + lane] = (uint16_t)h0;      g_q2[dst + 32 + lane] = (uint16_t)h1;
        g_q2[dst + 64 + lane] = (uint16_t)l0; g_q2[dst + 96 + lane] = (uint16_t)l1;
    }
    {   // k
        float v0 = g_qkv[src + CC + lane], v1 = g_qkv[src + CC + 32 + lane];
        float ss = v0 * v0 + v1 * v1;
#pragma unroll
        for (int off = 16; off > 0; off >>= 1) ss += __shfl_xor_sync(0xffffffffu, ss, off);
        float inv = 1.0f / fmaxf(sqrtf(ss), 1e-12f);
        uint32_t h0, l0, h1, l1;
        split2(v0 * inv, 0.f, h0, l0);
        split2(v1 * inv, 0.f, h1, l1);
        g_k2[dst + lane] = (uint16_t)h0;      g_k2[dst + 32 + lane] = (uint16_t)h1;
        g_k2[dst + 64 + lane] = (uint16_t)l0; g_k2[dst + 96 + lane] = (uint16_t)l1;
    }
}

// ---------------- V transpose: chunk c -> (B,H,d, c*128 + [vhi64|vlo64]) ----------------
__global__ __launch_bounds__(256) void vtrans_kernel()
{
    __shared__ float vt[64][65];
    int tid = threadIdx.x, c = blockIdx.x, bh = blockIdx.y;
    int b = bh >> 4, h = bh & 15;
    int rr = tid >> 2, cs = (tid & 3) * 16;
    const float* src = g_qkv + (size_t)(b * LL + c * 64 + rr) * (3 * CC) + 2 * CC + h * DD + cs;
#pragma unroll
    for (int j4 = 0; j4 < 4; j4++) {
        float4 v = *(const float4*)(src + j4 * 4);
        vt[cs + j4 * 4 + 0][rr] = v.x; vt[cs + j4 * 4 + 1][rr] = v.y;
        vt[cs + j4 * 4 + 2][rr] = v.z; vt[cs + j4 * 4 + 3][rr] = v.w;
    }
    __syncthreads();
    int d = tid >> 2, js = (tid & 3) * 16;
    uint32_t ho[8], lo[8];
#pragma unroll
    for (int j2 = 0; j2 < 8; j2++)
        split2(vt[d][js + j2 * 2], vt[d][js + j2 * 2 + 1], ho[j2], lo[j2]);
    size_t base = ((size_t)(bh * DD + d)) * (2 * LL) + (size_t)c * 128 + js;
    *(uint4*)(g_vt2 + base)      = *(uint4*)(ho);
    *(uint4*)(g_vt2 + base + 8)  = *(uint4*)(ho + 4);
    *(uint4*)(g_vt2 + base + 64) = *(uint4*)(lo);
    *(uint4*)(g_vt2 + base + 72) = *(uint4*)(lo + 4);
}

// ---------------- flash attention: 64-row Q tiles, 3-pass sub-block mma ----------------
#define FP2 136
#define FQ_OFF 0u
#define FPS_OFF 17408u
#define FK_OFF 34816u
#define FV_OFF 69632u
#define FLR_OFF 104448u
#define FLASH_SMEM 104960
#define KVSTG 17408u

__global__ __launch_bounds__(256, 2) void flash_mma(
    const float* __restrict__ attn_bias, const float* __restrict__ scale_mul)
{
    extern __shared__ __align__(16) uint8_t fsm[];
    uint32_t sb = smem_u32(fsm);
    const int tid = threadIdx.x, w = tid >> 5, lane = tid & 31;
    const int wr = w >> 1, wc = w & 1;          // 4 x 2 warp grid, 16x32 tiles
    const int g = lane >> 3, r = lane & 7;
    const int tq = lane >> 2, tr = lane & 3;
    const int q0 = blockIdx.x * 64;
    const int bh = blockIdx.y, b = bh >> 4, h = bh & 15;

    const uint16_t* Qg = g_q2 + ((size_t)bh * LL + q0) * 128;
    const uint16_t* Kg = g_k2 + ((size_t)bh * LL) * 128;
    const uint16_t* Vg = g_vt2 + (size_t)bh * DD * (2 * LL);

#pragma unroll
    for (int t = 0; t < 4; t++) {
        int j = tid + t * 256; int row = j >> 4, cc = (j & 15) * 8;
        cp16(sb + FQ_OFF + (uint32_t)(row * FP2 + cc) * 2, Qg + (size_t)row * 128 + cc);
    }
#define LOADKV(cidx, s) do { \
    _Pragma("unroll") \
    for (int t = 0; t < 4; t++) { \
        int j = tid + t * 256; int row = j >> 4, cc = (j & 15) * 8; \
        cp16(sb + FK_OFF + (s) * KVSTG + (uint32_t)(row * FP2 + cc) * 2, Kg + (size_t)((cidx) * 64 + row) * 128 + cc); \
        cp16(sb + FV_OFF + (s) * KVSTG + (uint32_t)(row * FP2 + cc) * 2, Vg + (size_t)row * (2 * LL) + (size_t)(cidx) * 128 + cc); \
    } } while (0)

    LOADKV(0, 0); CP_COMMIT();

    const float M = __expf(fminf(scale_mul[h], MAX_SM)) + __uint_as_float(g_bmax_bits);
    float oacc[4][4];
    float lsum[2] = {0.f, 0.f};
#pragma unroll
    for (int n = 0; n < 4; n++)
#pragma unroll
        for (int e = 0; e < 4; e++) oacc[n][e] = 0.f;

    const int SUBA[3] = {0, 0, 64}, SUBB[3] = {0, 64, 0};

    for (int c = 0; c < 32; c++) {
        int s = c & 1;
        if (c < 31) { LOADKV(c + 1, s ^ 1); CP_COMMIT(); CP_WAIT1(); }
        else CP_WAIT0();
        __syncthreads();

        // bias prefetch (hidden behind QK mma)
        int ktg = c * 64;
        float2 bb[4][2];
        {
            int rA = wr * 16 + tq;
#pragma unroll
            for (int nt = 0; nt < 4; nt++) {
                int cl = wc * 32 + nt * 8 + tr * 2;
                bb[nt][0] = *(const float2*)(attn_bias + (size_t)(q0 + rA) * LL + ktg + cl);
                bb[nt][1] = *(const float2*)(attn_bias + (size_t)(q0 + rA + 8) * LL + ktg + cl);
            }
        }

        float sacc[4][4];
#pragma unroll
        for (int n = 0; n < 4; n++)
#pragma unroll
            for (int e = 0; e < 4; e++) sacc[n][e] = 0.f;

        uint32_t bK = sb + FK_OFF + s * KVSTG;
#pragma unroll
        for (int p = 0; p < 3; p++) {
            int asub = SUBA[p], bsub = SUBB[p];
#pragma unroll
            for (int ks = 0; ks < 4; ks++) {
                uint32_t a0, a1, a2, a3;
                ldm4(a0, a1, a2, a3,
                     sb + FQ_OFF + (uint32_t)((wr * 16 + r + (g & 1) * 8) * FP2 + asub + ks * 16 + (g >> 1) * 8) * 2);
#pragma unroll
                for (int nj = 0; nj < 2; nj++) {
                    uint32_t b0, b1, b2, b3;
                    ldm4(b0, b1, b2, b3,
                         bK + (uint32_t)((wc * 32 + nj * 16 + (g >> 1) * 8 + r) * FP2 + bsub + ks * 16 + (g & 1) * 8) * 2);
                    mma16816(sacc[nj * 2 + 0], a0, a1, a2, a3, b0, b1);
                    mma16816(sacc[nj * 2 + 1], a0, a1, a2, a3, b2, b3);
                }
            }
        }

        // softmax (fixed shift) + P split to smem [phi|plo]
        {
            int rA = wr * 16 + tq;
#pragma unroll
            for (int nt = 0; nt < 4; nt++) {
                int cl = wc * 32 + nt * 8 + tr * 2;
                float p00 = __expf(sacc[nt][0] + bb[nt][0].x - M);
                float p01 = __expf(sacc[nt][1] + bb[nt][0].y - M);
                float p10 = __expf(sacc[nt][2] + bb[nt][1].x - M);
                float p11 = __expf(sacc[nt][3] + bb[nt][1].y - M);
                lsum[0] += p00 + p01;
                lsum[1] += p10 + p11;
                uint32_t hA, lA, hB, lB;
                split2(p00, p01, hA, lA);
                split2(p10, p11, hB, lB);
                uint32_t a0 = sb + FPS_OFF + (uint32_t)(rA * FP2 + cl) * 2;
                uint32_t a1 = sb + FPS_OFF + (uint32_t)((rA + 8) * FP2 + cl) * 2;
                st32s(a0, hA); st32s(a0 + 128, lA);
                st32s(a1, hB); st32s(a1 + 128, lB);
            }
        }
        __syncthreads();

        uint32_t bV = sb + FV_OFF + s * KVSTG;
#pragma unroll
        for (int p = 0; p < 3; p++) {
            int asub = SUBA[p], bsub = SUBB[p];
#pragma unroll
            for (int ks = 0; ks < 4; ks++) {
                uint32_t a0, a1, a2, a3;
                ldm4(a0, a1, a2, a3,
                     sb + FPS_OFF + (uint32_t)((wr * 16 + r + (g & 1) * 8) * FP2 + asub + ks * 16 + (g >> 1) * 8) * 2);
#pragma unroll
                for (int nj = 0; nj < 2; nj++) {
                    uint32_t b0, b1, b2, b3;
                    ldm4(b0, b1, b2, b3,
                         bV + (uint32_t)((wc * 32 + nj * 16 + (g >> 1) * 8 + r) * FP2 + bsub + ks * 16 + (g & 1) * 8) * 2);
                    mma16816(oacc[nj * 2 + 0], a0, a1, a2, a3, b0, b1);
                    mma16816(oacc[nj * 2 + 1], a0, a1, a2, a3, b2, b3);
                }
            }
        }
        __syncthreads();
    }
#undef LOADKV

    // row-sum reduce: over tr lanes then across wc warps
#pragma unroll
    for (int a = 0; a < 2; a++) {
        lsum[a] += __shfl_xor_sync(0xffffffffu, lsum[a], 1);
        lsum[a] += __shfl_xor_sync(0xffffffffu, lsum[a], 2);
    }
    float* lred = (float*)(fsm + FLR_OFF);
    if (tr == 0) {
        lred[(wr * 16 + tq) * 2 + wc] = lsum[0];
        lred[(wr * 16 + tq + 8) * 2 + wc] = lsum[1];
    }
    __syncthreads();
    {
        int rA = wr * 16 + tq;
        float inv0 = 1.f / (lred[rA * 2] + lred[rA * 2 + 1]);
        float inv1 = 1.f / (lred[(rA + 8) * 2] + lred[(rA + 8) * 2 + 1]);
        size_t r0g = (size_t)(b * LL + q0 + rA) * CC + h * DD;
        size_t r1g = (size_t)(b * LL + q0 + rA + 8) * CC + h * DD;
#pragma unroll
        for (int nt = 0; nt < 4; nt++) {
            int cl = wc * 32 + nt * 8 + tr * 2;
            uint32_t hA, lA, hB, lB;
            split2(oacc[nt][0] * inv0, oacc[nt][1] * inv0, hA, lA);
            split2(oacc[nt][2] * inv1, oacc[nt][3] * inv1, hB, lB);
            *(uint32_t*)(g_ah + r0g + cl) = hA;
            *(uint32_t*)(g_al + r0g + cl) = lA;
            *(uint32_t*)(g_ah + r1g + cl) = hB;
            *(uint32_t*)(g_al + r1g + cl) = lB;
        }
    }
}

extern "C" void kernel_launch(void* const* d_in, const int* in_sizes, int n_in,
                              void* d_out, int out_size)
{
    const float* x         = (const float*)d_in[0];
    const float* attn_bias = (const float*)d_in[1];
    const float* W_qkv     = (const float*)d_in[2];
    const float* q_bias    = (const float*)d_in[3];
    const float* v_bias    = (const float*)d_in[4];
    const float* scale_mul = (const float*)d_in[5];
    const float* W_proj    = (const float*)d_in[6];
    const float* b_proj    = (const float*)d_in[7];
    float* out = (float*)d_out;

    float* qkv_p;
    uint16_t *xh, *xl, *wqh, *wql, *wph, *wpl, *ah, *al;
    cudaGetSymbolAddress((void**)&qkv_p, g_qkv);
    cudaGetSymbolAddress((void**)&xh, g_xh);   cudaGetSymbolAddress((void**)&xl, g_xl);
    cudaGetSymbolAddress((void**)&wqh, g_wqh); cudaGetSymbolAddress((void**)&wql, g_wql);
    cudaGetSymbolAddress((void**)&wph, g_wph); cudaGetSymbolAddress((void**)&wpl, g_wpl);
    cudaGetSymbolAddress((void**)&ah, g_ah);   cudaGetSymbolAddress((void**)&al, g_al);

    cudaFuncSetAttribute(gemm_bf16<0>, cudaFuncAttributeMaxDynamicSharedMemorySize, GEMM_SMEM);
    cudaFuncSetAttribute(gemm_bf16<1>, cudaFuncAttributeMaxDynamicSharedMemorySize, GEMM_SMEM);
    cudaFuncSetAttribute(flash_mma, cudaFuncAttributeMaxDynamicSharedMemorySize, FLASH_SMEM);

    // launches 1-3: splits; launch 4: gemm0 (profiled slot)
    split_kernel<<<(MM * CC / 4 + 255) / 256, 256>>>(x, xh, xl, MM * CC / 4);
    split_kernel<<<(3 * CC * CC / 4 + 255) / 256, 256>>>(W_qkv, wqh, wql, 3 * CC * CC / 4);
    split_kernel<<<(CC * CC / 4 + 255) / 256, 256>>>(W_proj, wph, wpl, CC * CC / 4);

    gemm_bf16<0><<<dim3(3 * CC / 128, MM / 128), 128, GEMM_SMEM>>>(
        xh, xl, wqh, wql, q_bias, v_bias, qkv_p, 3 * CC);

    bmax_reduce<<<512, 256>>>(attn_bias, LL * LL / 4);
    norm_split_kernel<<<(BB * LL * HH * 32) / 256, 256>>>(scale_mul);
    vtrans_kernel<<<dim3(LL / 64, BB * HH), 256>>>();

    flash_mma<<<dim3(LL / 64, BB * HH), 256, FLASH_SMEM>>>(attn_bias, scale_mul);

    gemm_bf16<1><<<dim3(CC / 128, MM / 128), 128, GEMM_SMEM>>>(
        ah, al, wph, wpl, b_proj, nullptr, out, CC);
}

// round 8
// speedup vs baseline: 2.5560x; 1.0674x over previous
#include <cuda_runtime.h>
#include <math.h>
#include <stdint.h>

#define BB 2
#define LL 2048
#define CC 1024
#define HH 16
#define DD 64
#define MM (BB * LL)
#define KE 3072
#define MAX_SM 4.6051701859880913680f

__device__ float    g_qkv[MM * 3 * CC];
__device__ uint16_t g_xh[MM * CC],  g_xl[MM * CC];
__device__ uint16_t g_wqh[3 * CC * CC], g_wql[3 * CC * CC];
__device__ uint16_t g_wph[CC * CC], g_wpl[CC * CC];
__device__ uint16_t g_q2[BB * HH * LL * 128];
__device__ uint16_t g_k2[BB * HH * LL * 128];
__device__ uint16_t g_vt2[(size_t)BB * HH * DD * 2 * LL];
__device__ uint16_t g_ah[MM * CC], g_al[MM * CC];
__device__ unsigned g_bmax_bits;   // zero at load; atomicMax idempotent per replay

__device__ __forceinline__ uint32_t smem_u32(const void* p) {
    uint32_t a;
    asm("{ .reg .u64 t; cvta.to.shared.u64 t, %1; cvt.u32.u64 %0, t; }" : "=r"(a) : "l"(p));
    return a;
}
__device__ __forceinline__ void cp16(uint32_t dst, const void* src) {
    asm volatile("cp.async.cg.shared.global [%0], [%1], 16;" :: "r"(dst), "l"(src));
}
#define CP_COMMIT() asm volatile("cp.async.commit_group;")
#define CP_WAIT0()  asm volatile("cp.async.wait_group 0;" ::: "memory")
#define CP_WAIT1()  asm volatile("cp.async.wait_group 1;" ::: "memory")

__device__ __forceinline__ void ldm4(uint32_t& r0, uint32_t& r1, uint32_t& r2, uint32_t& r3, uint32_t a) {
    asm volatile("ldmatrix.sync.aligned.m8n8.x4.shared.b16 {%0,%1,%2,%3}, [%4];"
                 : "=r"(r0), "=r"(r1), "=r"(r2), "=r"(r3) : "r"(a));
}
__device__ __forceinline__ void mma16816(float* c, uint32_t a0, uint32_t a1, uint32_t a2, uint32_t a3,
                                         uint32_t b0, uint32_t b1) {
    asm volatile("mma.sync.aligned.m16n8k16.row.col.f32.bf16.bf16.f32 "
                 "{%0,%1,%2,%3}, {%4,%5,%6,%7}, {%8,%9}, {%0,%1,%2,%3};"
                 : "+f"(c[0]), "+f"(c[1]), "+f"(c[2]), "+f"(c[3])
                 : "r"(a0), "r"(a1), "r"(a2), "r"(a3), "r"(b0), "r"(b1));
}
__device__ __forceinline__ void st32s(uint32_t a, uint32_t v) {
    asm volatile("st.shared.b32 [%0], %1;" :: "r"(a), "r"(v) : "memory");
}
__device__ __forceinline__ uint32_t pack_bf(float lo, float hi) {
    uint32_t r;
    asm("cvt.rn.bf16x2.f32 %0, %1, %2;" : "=r"(r) : "f"(hi), "f"(lo));
    return r;
}
__device__ __forceinline__ void split2(float a, float b, uint32_t& hi, uint32_t& lo) {
    hi = pack_bf(a, b);
    float ha = __uint_as_float(hi << 16);
    float hb = __uint_as_float(hi & 0xFFFF0000u);
    lo = pack_bf(a - ha, b - hb);
}

__global__ __launch_bounds__(256) void split_kernel(
    const float* __restrict__ in, uint16_t* __restrict__ hi,
    uint16_t* __restrict__ lo, int n4)
{
    int i = blockIdx.x * 256 + threadIdx.x;
    if (i >= n4) return;
    float4 v = ((const float4*)in)[i];
    uint32_t h01, l01, h23, l23;
    split2(v.x, v.y, h01, l01);
    split2(v.z, v.w, h23, l23);
    uint2 hv; hv.x = h01; hv.y = h23;
    uint2 lv; lv.x = l01; lv.y = l23;
    ((uint2*)hi)[i] = hv;
    ((uint2*)lo)[i] = lv;
}

__global__ __launch_bounds__(256) void bmax_reduce(const float* __restrict__ b, int n4)
{
    float m = 0.f;
    for (int i = blockIdx.x * 256 + threadIdx.x; i < n4; i += gridDim.x * 256) {
        float4 v = ((const float4*)b)[i];
        m = fmaxf(m, fmaxf(fmaxf(fabsf(v.x), fabsf(v.y)), fmaxf(fabsf(v.z), fabsf(v.w))));
    }
#pragma unroll
    for (int off = 16; off > 0; off >>= 1)
        m = fmaxf(m, __shfl_xor_sync(0xffffffffu, m, off));
    if ((threadIdx.x & 31) == 0) atomicMax(&g_bmax_bits, __float_as_uint(m));
}

// ---------------- GEMM: C = (Ahi+Alo)(Bhi+Blo)^T via 3-term map over kt=3072 ----------------
// CTA 128x128, 4 warps (64x64 each), BK=64, 2-stage cp.async, 3 CTAs/SM.
#define GP 72
#define GEMM_SMEM (2 * 256 * GP * 2)

template <int MODE>
__global__ __launch_bounds__(128, 3) void gemm_bf16(
    const uint16_t* __restrict__ Ahi, const uint16_t* __restrict__ Alo,
    const uint16_t* __restrict__ Bhi, const uint16_t* __restrict__ Blo,
    const float* __restrict__ bias1, const float* __restrict__ bias2,
    float* __restrict__ C, int N)
{
    extern __shared__ __align__(16) uint8_t gsm[];
    uint32_t sA = smem_u32(gsm);
    uint32_t sB = sA + 2 * 128 * GP * 2;
    const int tid = threadIdx.x, w = tid >> 5, lane = tid & 31;
    const int m0 = blockIdx.y * 128, n0 = blockIdx.x * 128;
    const int wr = w >> 1, wc = w & 1;
    const int mw = wr * 64, nw = wc * 64;
    const int g = lane >> 3, r = lane & 7;
    const int tq = lane >> 2, tr = lane & 3;

    float acc[4][8][4];
#pragma unroll
    for (int a = 0; a < 4; a++)
#pragma unroll
        for (int b = 0; b < 8; b++)
#pragma unroll
            for (int c = 0; c < 4; c++) acc[a][b][c] = 0.f;

#define GLOAD(s, kt) do { \
    const uint16_t* PA = ((kt) < 2048) ? Ahi : Alo; \
    const uint16_t* PB = ((kt) < 1024 || (kt) >= 2048) ? Bhi : Blo; \
    int ka = ((kt) < 2048) ? ((kt) & 1023) : ((kt) - 2048); \
    int kb = (kt) & 1023; \
    _Pragma("unroll") \
    for (int t = 0; t < 16; t++) { \
        int j = tid + t * 128; int row = j >> 3, cc = (j & 7) * 8; \
        if (row < 128) \
            cp16(sA + (uint32_t)(((s) * 128 + row) * GP + cc) * 2, PA + (size_t)(m0 + row) * 1024 + ka + cc); \
        else \
            cp16(sB + (uint32_t)(((s) * 128 + row - 128) * GP + cc) * 2, PB + (size_t)(n0 + row - 128) * 1024 + kb + cc); \
    } } while (0)

    const int NK = KE / 64;   // 48
    GLOAD(0, 0); CP_COMMIT();

    for (int it = 0; it < NK; it++) {
        int s = it & 1;
        CP_WAIT0();
        __syncthreads();
        if (it + 1 < NK) { GLOAD(s ^ 1, (it + 1) * 64); CP_COMMIT(); }
        uint32_t baseA = sA + (uint32_t)(s * 128 * GP) * 2;
        uint32_t baseB = sB + (uint32_t)(s * 128 * GP) * 2;
#pragma unroll
        for (int ks = 0; ks < 4; ks++) {
            uint32_t af[4][4];
#pragma unroll
            for (int mi = 0; mi < 4; mi++)
                ldm4(af[mi][0], af[mi][1], af[mi][2], af[mi][3],
                     baseA + (uint32_t)((mw + mi * 16 + r + (g & 1) * 8) * GP + ks * 16 + (g >> 1) * 8) * 2);
#pragma unroll
            for (int nj = 0; nj < 4; nj++) {
                uint32_t b0, b1, b2, b3;
                ldm4(b0, b1, b2, b3,
                     baseB + (uint32_t)((nw + nj * 16 + (g >> 1) * 8 + r) * GP + ks * 16 + (g & 1) * 8) * 2);
#pragma unroll
                for (int mi = 0; mi < 4; mi++) {
                    mma16816(acc[mi][nj * 2 + 0], af[mi][0], af[mi][1], af[mi][2], af[mi][3], b0, b1);
                    mma16816(acc[mi][nj * 2 + 1], af[mi][0], af[mi][1], af[mi][2], af[mi][3], b2, b3);
                }
            }
        }
    }
#undef GLOAD

#pragma unroll
    for (int mi = 0; mi < 4; mi++) {
#pragma unroll
        for (int nt = 0; nt < 8; nt++) {
            int colg = n0 + nw + nt * 8 + tr * 2;
            float b0, b1;
            if (MODE == 0) {
                b0 = (colg < CC) ? bias1[colg] : ((colg < 2 * CC) ? 0.f : bias2[colg - 2 * CC]);
                int c1 = colg + 1;
                b1 = (c1 < CC) ? bias1[c1] : ((c1 < 2 * CC) ? 0.f : bias2[c1 - 2 * CC]);
            } else { b0 = bias1[colg]; b1 = bias1[colg + 1]; }
            int rA = m0 + mw + mi * 16 + tq;
            float2 v0, v1;
            v0.x = acc[mi][nt][0] + b0; v0.y = acc[mi][nt][1] + b1;
            v1.x = acc[mi][nt][2] + b0; v1.y = acc[mi][nt][3] + b1;
            *(float2*)(C + (size_t)rA * N + colg) = v0;
            *(float2*)(C + (size_t)(rA + 8) * N + colg) = v1;
        }
    }
}

// ---------------- normalize + split q,k -> (B,H,L,[hi64|lo64]) ----------------
__global__ __launch_bounds__(256) void norm_split_kernel(const float* __restrict__ scale_mul)
{
    int gwarp = (blockIdx.x * 256 + threadIdx.x) >> 5;
    int lane = threadIdx.x & 31;
    if (gwarp >= BB * LL * HH) return;
    int b = gwarp / (LL * HH), rem = gwarp % (LL * HH);
    int l = rem / HH, h = rem % HH;
    size_t src = (size_t)(b * LL + l) * (3 * CC) + h * DD;
    size_t dst = ((size_t)((b * HH + h) * LL) + l) * 128;
    float sm = __expf(fminf(scale_mul[h], MAX_SM));

    {
        float v0 = g_qkv[src + lane], v1 = g_qkv[src + 32 + lane];
        float ss = v0 * v0 + v1 * v1;
#pragma unroll
        for (int off = 16; off > 0; off >>= 1) ss += __shfl_xor_sync(0xffffffffu, ss, off);
        float inv = sm / fmaxf(sqrtf(ss), 1e-12f);
        uint32_t h0, l0, h1, l1;
        split2(v0 * inv, 0.f, h0, l0);
        split2(v1 * inv, 0.f, h1, l1);
        g_q2[dst + lane] = (uint16_t)h0;      g_q2[dst + 32 + lane] = (uint16_t)h1;
        g_q2[dst + 64 + lane] = (uint16_t)l0; g_q2[dst + 96 + lane] = (uint16_t)l1;
    }
    {
        float v0 = g_qkv[src + CC + lane], v1 = g_qkv[src + CC + 32 + lane];
        float ss = v0 * v0 + v1 * v1;
#pragma unroll
        for (int off = 16; off > 0; off >>= 1) ss += __shfl_xor_sync(0xffffffffu, ss, off);
        float inv = 1.0f / fmaxf(sqrtf(ss), 1e-12f);
        uint32_t h0, l0, h1, l1;
        split2(v0 * inv, 0.f, h0, l0);
        split2(v1 * inv, 0.f, h1, l1);
        g_k2[dst + lane] = (uint16_t)h0;      g_k2[dst + 32 + lane] = (uint16_t)h1;
        g_k2[dst + 64 + lane] = (uint16_t)l0; g_k2[dst + 96 + lane] = (uint16_t)l1;
    }
}

// ---------------- V transpose ----------------
__global__ __launch_bounds__(256) void vtrans_kernel()
{
    __shared__ float vt[64][65];
    int tid = threadIdx.x, c = blockIdx.x, bh = blockIdx.y;
    int b = bh >> 4, h = bh & 15;
    int rr = tid >> 2, cs = (tid & 3) * 16;
    const float* src = g_qkv + (size_t)(b * LL + c * 64 + rr) * (3 * CC) + 2 * CC + h * DD + cs;
#pragma unroll
    for (int j4 = 0; j4 < 4; j4++) {
        float4 v = *(const float4*)(src + j4 * 4);
        vt[cs + j4 * 4 + 0][rr] = v.x; vt[cs + j4 * 4 + 1][rr] = v.y;
        vt[cs + j4 * 4 + 2][rr] = v.z; vt[cs + j4 * 4 + 3][rr] = v.w;
    }
    __syncthreads();
    int d = tid >> 2, js = (tid & 3) * 16;
    uint32_t ho[8], lo[8];
#pragma unroll
    for (int j2 = 0; j2 < 8; j2++)
        split2(vt[d][js + j2 * 2], vt[d][js + j2 * 2 + 1], ho[j2], lo[j2]);
    size_t base = ((size_t)(bh * DD + d)) * (2 * LL) + (size_t)c * 128 + js;
    *(uint4*)(g_vt2 + base)      = *(uint4*)(ho);
    *(uint4*)(g_vt2 + base + 8)  = *(uint4*)(ho + 4);
    *(uint4*)(g_vt2 + base + 64) = *(uint4*)(lo);
    *(uint4*)(g_vt2 + base + 72) = *(uint4*)(lo + 4);
}

// ---------------- flash attention: 64-row Q tiles, 3-pass sub-block mma ----------------
#define FP2 136
#define FQ_OFF 0u
#define FPS_OFF 17408u
#define FK_OFF 34816u
#define FV_OFF 69632u
#define FLR_OFF 104448u
#define FLASH_SMEM 104960
#define KVSTG 17408u

__global__ __launch_bounds__(256, 2) void flash_mma(
    const float* __restrict__ attn_bias, const float* __restrict__ scale_mul)
{
    extern __shared__ __align__(16) uint8_t fsm[];
    uint32_t sb = smem_u32(fsm);
    const int tid = threadIdx.x, w = tid >> 5, lane = tid & 31;
    const int wr = w >> 1, wc = w & 1;
    const int g = lane >> 3, r = lane & 7;
    const int tq = lane >> 2, tr = lane & 3;
    const int q0 = blockIdx.x * 64;
    const int bh = blockIdx.y, b = bh >> 4, h = bh & 15;

    const uint16_t* Qg = g_q2 + ((size_t)bh * LL + q0) * 128;
    const uint16_t* Kg = g_k2 + ((size_t)bh * LL) * 128;
    const uint16_t* Vg = g_vt2 + (size_t)bh * DD * (2 * LL);

#pragma unroll
    for (int t = 0; t < 4; t++) {
        int j = tid + t * 256; int row = j >> 4, cc = (j & 15) * 8;
        cp16(sb + FQ_OFF + (uint32_t)(row * FP2 + cc) * 2, Qg + (size_t)row * 128 + cc);
    }
#define LOADKV(cidx, s) do { \
    _Pragma("unroll") \
    for (int t = 0; t < 4; t++) { \
        int j = tid + t * 256; int row = j >> 4, cc = (j & 15) * 8; \
        cp16(sb + FK_OFF + (s) * KVSTG + (uint32_t)(row * FP2 + cc) * 2, Kg + (size_t)((cidx) * 64 + row) * 128 + cc); \
        cp16(sb + FV_OFF + (s) * KVSTG + (uint32_t)(row * FP2 + cc) * 2, Vg + (size_t)row * (2 * LL) + (size_t)(cidx) * 128 + cc); \
    } } while (0)

    LOADKV(0, 0); CP_COMMIT();

    const float M = __expf(fminf(scale_mul[h], MAX_SM)) + __uint_as_float(g_bmax_bits);
    float oacc[4][4];
    float lsum[2] = {0.f, 0.f};
#pragma unroll
    for (int n = 0; n < 4; n++)
#pragma unroll
        for (int e = 0; e < 4; e++) oacc[n][e] = 0.f;

    const int SUBA[3] = {0, 0, 64}, SUBB[3] = {0, 64, 0};

    for (int c = 0; c < 32; c++) {
        int s = c & 1;
        CP_WAIT0();
        __syncthreads();     // stage s ready AND all warps done with stage s^1 + P from prev chunk
        if (c < 31) { LOADKV(c + 1, s ^ 1); CP_COMMIT(); }

        int ktg = c * 64;
        float2 bb[4][2];
        {
            int rA = wr * 16 + tq;
#pragma unroll
            for (int nt = 0; nt < 4; nt++) {
                int cl = wc * 32 + nt * 8 + tr * 2;
                bb[nt][0] = *(const float2*)(attn_bias + (size_t)(q0 + rA) * LL + ktg + cl);
                bb[nt][1] = *(const float2*)(attn_bias + (size_t)(q0 + rA + 8) * LL + ktg + cl);
            }
        }

        float sacc[4][4];
#pragma unroll
        for (int n = 0; n < 4; n++)
#pragma unroll
            for (int e = 0; e < 4; e++) sacc[n][e] = 0.f;

        uint32_t bK = sb + FK_OFF + s * KVSTG;
#pragma unroll
        for (int p = 0; p < 3; p++) {
            int asub = SUBA[p], bsub = SUBB[p];
#pragma unroll
            for (int ks = 0; ks < 4; ks++) {
                uint32_t a0, a1, a2, a3;
                ldm4(a0, a1, a2, a3,
                     sb + FQ_OFF + (uint32_t)((wr * 16 + r + (g & 1) * 8) * FP2 + asub + ks * 16 + (g >> 1) * 8) * 2);
#pragma unroll
                for (int nj = 0; nj < 2; nj++) {
                    uint32_t b0, b1, b2, b3;
                    ldm4(b0, b1, b2, b3,
                         bK + (uint32_t)((wc * 32 + nj * 16 + (g >> 1) * 8 + r) * FP2 + bsub + ks * 16 + (g & 1) * 8) * 2);
                    mma16816(sacc[nj * 2 + 0], a0, a1, a2, a3, b0, b1);
                    mma16816(sacc[nj * 2 + 1], a0, a1, a2, a3, b2, b3);
                }
            }
        }

        {
            int rA = wr * 16 + tq;
#pragma unroll
            for (int nt = 0; nt < 4; nt++) {
                int cl = wc * 32 + nt * 8 + tr * 2;
                float p00 = __expf(sacc[nt][0] + bb[nt][0].x - M);
                float p01 = __expf(sacc[nt][1] + bb[nt][0].y - M);
                float p10 = __expf(sacc[nt][2] + bb[nt][1].x - M);
                float p11 = __expf(sacc[nt][3] + bb[nt][1].y - M);
                lsum[0] += p00 + p01;
                lsum[1] += p10 + p11;
                uint32_t hA, lA, hB, lB;
                split2(p00, p01, hA, lA);
                split2(p10, p11, hB, lB);
                uint32_t a0 = sb + FPS_OFF + (uint32_t)(rA * FP2 + cl) * 2;
                uint32_t a1 = sb + FPS_OFF + (uint32_t)((rA + 8) * FP2 + cl) * 2;
                st32s(a0, hA); st32s(a0 + 128, lA);
                st32s(a1, hB); st32s(a1 + 128, lB);
            }
        }
        __syncthreads();     // P visible to all warps before PV

        uint32_t bV = sb + FV_OFF + s * KVSTG;
#pragma unroll
        for (int p = 0; p < 3; p++) {
            int asub = SUBA[p], bsub = SUBB[p];
#pragma unroll
            for (int ks = 0; ks < 4; ks++) {
                uint32_t a0, a1, a2, a3;
                ldm4(a0, a1, a2, a3,
                     sb + FPS_OFF + (uint32_t)((wr * 16 + r + (g & 1) * 8) * FP2 + asub + ks * 16 + (g >> 1) * 8) * 2);
#pragma unroll
                for (int nj = 0; nj < 2; nj++) {
                    uint32_t b0, b1, b2, b3;
                    ldm4(b0, b1, b2, b3,
                         bV + (uint32_t)((wc * 32 + nj * 16 + (g >> 1) * 8 + r) * FP2 + bsub + ks * 16 + (g & 1) * 8) * 2);
                    mma16816(oacc[nj * 2 + 0], a0, a1, a2, a3, b0, b1);
                    mma16816(oacc[nj * 2 + 1], a0, a1, a2, a3, b2, b3);
                }
            }
        }
        // no trailing sync: next chunk's top sync orders PV reads before overwrites
    }
#undef LOADKV

#pragma unroll
    for (int a = 0; a < 2; a++) {
        lsum[a] += __shfl_xor_sync(0xffffffffu, lsum[a], 1);
        lsum[a] += __shfl_xor_sync(0xffffffffu, lsum[a], 2);
    }
    float* lred = (float*)(fsm + FLR_OFF);
    __syncthreads();
    if (tr == 0) {
        lred[(wr * 16 + tq) * 2 + wc] = lsum[0];
        lred[(wr * 16 + tq + 8) * 2 + wc] = lsum[1];
    }
    __syncthreads();
    {
        int rA = wr * 16 + tq;
        float inv0 = 1.f / (lred[rA * 2] + lred[rA * 2 + 1]);
        float inv1 = 1.f / (lred[(rA + 8) * 2] + lred[(rA + 8) * 2 + 1]);
        size_t r0g = (size_t)(b * LL + q0 + rA) * CC + h * DD;
        size_t r1g = (size_t)(b * LL + q0 + rA + 8) * CC + h * DD;
#pragma unroll
        for (int nt = 0; nt < 4; nt++) {
            int cl = wc * 32 + nt * 8 + tr * 2;
            uint32_t hA, lA, hB, lB;
            split2(oacc[nt][0] * inv0, oacc[nt][1] * inv0, hA, lA);
            split2(oacc[nt][2] * inv1, oacc[nt][3] * inv1, hB, lB);
            *(uint32_t*)(g_ah + r0g + cl) = hA;
            *(uint32_t*)(g_al + r0g + cl) = lA;
            *(uint32_t*)(g_ah + r1g + cl) = hB;
            *(uint32_t*)(g_al + r1g + cl) = lB;
        }
    }
}

extern "C" void kernel_launch(void* const* d_in, const int* in_sizes, int n_in,
                              void* d_out, int out_size)
{
    const float* x         = (const float*)d_in[0];
    const float* attn_bias = (const float*)d_in[1];
    const float* W_qkv     = (const float*)d_in[2];
    const float* q_bias    = (const float*)d_in[3];
    const float* v_bias    = (const float*)d_in[4];
    const float* scale_mul = (const float*)d_in[5];
    const float* W_proj    = (const float*)d_in[6];
    const float* b_proj    = (const float*)d_in[7];
    float* out = (float*)d_out;

    float* qkv_p;
    uint16_t *xh, *xl, *wqh, *wql, *wph, *wpl, *ah, *al;
    cudaGetSymbolAddress((void**)&qkv_p, g_qkv);
    cudaGetSymbolAddress((void**)&xh, g_xh);   cudaGetSymbolAddress((void**)&xl, g_xl);
    cudaGetSymbolAddress((void**)&wqh, g_wqh); cudaGetSymbolAddress((void**)&wql, g_wql);
    cudaGetSymbolAddress((void**)&wph, g_wph); cudaGetSymbolAddress((void**)&wpl, g_wpl);
    cudaGetSymbolAddress((void**)&ah, g_ah);   cudaGetSymbolAddress((void**)&al, g_al);

    cudaFuncSetAttribute(gemm_bf16<0>, cudaFuncAttributeMaxDynamicSharedMemorySize, GEMM_SMEM);
    cudaFuncSetAttribute(gemm_bf16<1>, cudaFuncAttributeMaxDynamicSharedMemorySize, GEMM_SMEM);
    cudaFuncSetAttribute(flash_mma, cudaFuncAttributeMaxDynamicSharedMemorySize, FLASH_SMEM);

    split_kernel<<<(MM * CC / 4 + 255) / 256, 256>>>(x, xh, xl, MM * CC / 4);
    split_kernel<<<(3 * CC * CC / 4 + 255) / 256, 256>>>(W_qkv, wqh, wql, 3 * CC * CC / 4);
    split_kernel<<<(CC * CC / 4 + 255) / 256, 256>>>(W_proj, wph, wpl, CC * CC / 4);

    gemm_bf16<0><<<dim3(3 * CC / 128, MM / 128), 128, GEMM_SMEM>>>(
        xh, xl, wqh, wql, q_bias, v_bias, qkv_p, 3 * CC);

    bmax_reduce<<<512, 256>>>(attn_bias, LL * LL / 4);
    norm_split_kernel<<<(BB * LL * HH * 32) / 256, 256>>>(scale_mul);
    vtrans_kernel<<<dim3(LL / 64, BB * HH), 256>>>();

    flash_mma<<<dim3(LL / 64, BB * HH), 256, FLASH_SMEM>>>(attn_bias, scale_mul);

    gemm_bf16<1><<<dim3(CC / 128, MM / 128), 128, GEMM_SMEM>>>(
        ah, al, wph, wpl, b_proj, nullptr, out, CC);
}

// round 9
// speedup vs baseline: 2.5702x; 1.0055x over previous
#include <cuda_runtime.h>
#include <math.h>
#include <stdint.h>

#define BB 2
#define LL 2048
#define CC 1024
#define HH 16
#define DD 64
#define MM (BB * LL)
#define KE 3072
#define MAX_SM 4.6051701859880913680f

__device__ float    g_qkv[MM * 3 * CC];
__device__ uint16_t g_xh[MM * CC],  g_xl[MM * CC];
__device__ uint16_t g_wqh[3 * CC * CC], g_wql[3 * CC * CC];
__device__ uint16_t g_wph[CC * CC], g_wpl[CC * CC];
__device__ uint16_t g_q2[BB * HH * LL * 128];
__device__ uint16_t g_k2[BB * HH * LL * 128];
__device__ uint16_t g_vt2[(size_t)BB * HH * DD * 2 * LL];
__device__ uint16_t g_ah[MM * CC], g_al[MM * CC];
__device__ unsigned g_bmax_bits;   // zero at load; atomicMax idempotent per replay

__device__ __forceinline__ uint32_t smem_u32(const void* p) {
    uint32_t a;
    asm("{ .reg .u64 t; cvta.to.shared.u64 t, %1; cvt.u32.u64 %0, t; }" : "=r"(a) : "l"(p));
    return a;
}
__device__ __forceinline__ void cp16(uint32_t dst, const void* src) {
    asm volatile("cp.async.cg.shared.global [%0], [%1], 16;" :: "r"(dst), "l"(src));
}
#define CP_COMMIT() asm volatile("cp.async.commit_group;")
#define CP_WAIT0()  asm volatile("cp.async.wait_group 0;" ::: "memory")
#define CP_WAIT1()  asm volatile("cp.async.wait_group 1;" ::: "memory")

__device__ __forceinline__ void ldm4(uint32_t& r0, uint32_t& r1, uint32_t& r2, uint32_t& r3, uint32_t a) {
    asm volatile("ldmatrix.sync.aligned.m8n8.x4.shared.b16 {%0,%1,%2,%3}, [%4];"
                 : "=r"(r0), "=r"(r1), "=r"(r2), "=r"(r3) : "r"(a));
}
__device__ __forceinline__ void mma16816(float* c, uint32_t a0, uint32_t a1, uint32_t a2, uint32_t a3,
                                         uint32_t b0, uint32_t b1) {
    asm volatile("mma.sync.aligned.m16n8k16.row.col.f32.bf16.bf16.f32 "
                 "{%0,%1,%2,%3}, {%4,%5,%6,%7}, {%8,%9}, {%0,%1,%2,%3};"
                 : "+f"(c[0]), "+f"(c[1]), "+f"(c[2]), "+f"(c[3])
                 : "r"(a0), "r"(a1), "r"(a2), "r"(a3), "r"(b0), "r"(b1));
}
__device__ __forceinline__ void st32s(uint32_t a, uint32_t v) {
    asm volatile("st.shared.b32 [%0], %1;" :: "r"(a), "r"(v) : "memory");
}
__device__ __forceinline__ uint32_t pack_bf(float lo, float hi) {
    uint32_t r;
    asm("cvt.rn.bf16x2.f32 %0, %1, %2;" : "=r"(r) : "f"(hi), "f"(lo));
    return r;
}
__device__ __forceinline__ void split2(float a, float b, uint32_t& hi, uint32_t& lo) {
    hi = pack_bf(a, b);
    float ha = __uint_as_float(hi << 16);
    float hb = __uint_as_float(hi & 0xFFFF0000u);
    lo = pack_bf(a - ha, b - hb);
}

__global__ __launch_bounds__(256) void split_kernel(
    const float* __restrict__ in, uint16_t* __restrict__ hi,
    uint16_t* __restrict__ lo, int n4)
{
    int i = blockIdx.x * 256 + threadIdx.x;
    if (i >= n4) return;
    float4 v = ((const float4*)in)[i];
    uint32_t h01, l01, h23, l23;
    split2(v.x, v.y, h01, l01);
    split2(v.z, v.w, h23, l23);
    uint2 hv; hv.x = h01; hv.y = h23;
    uint2 lv; lv.x = l01; lv.y = l23;
    ((uint2*)hi)[i] = hv;
    ((uint2*)lo)[i] = lv;
}

__global__ __launch_bounds__(256) void bmax_reduce(const float* __restrict__ b, int n4)
{
    float m = 0.f;
    for (int i = blockIdx.x * 256 + threadIdx.x; i < n4; i += gridDim.x * 256) {
        float4 v = ((const float4*)b)[i];
        m = fmaxf(m, fmaxf(fmaxf(fabsf(v.x), fabsf(v.y)), fmaxf(fabsf(v.z), fabsf(v.w))));
    }
#pragma unroll
    for (int off = 16; off > 0; off >>= 1)
        m = fmaxf(m, __shfl_xor_sync(0xffffffffu, m, off));
    if ((threadIdx.x & 31) == 0) atomicMax(&g_bmax_bits, __float_as_uint(m));
}

// ---------------- GEMM: C = (Ahi+Alo)(Bhi+Blo)^T via 3-term map over kt=3072 ----------------
// CTA 128x128, 4 warps (64x64 each), BK=64, 3-stage cp.async, 2 CTAs/SM.
#define GP 72
#define GEMM_SMEM (3 * 256 * GP * 2)

template <int MODE>
__global__ __launch_bounds__(128, 2) void gemm_bf16(
    const uint16_t* __restrict__ Ahi, const uint16_t* __restrict__ Alo,
    const uint16_t* __restrict__ Bhi, const uint16_t* __restrict__ Blo,
    const float* __restrict__ bias1, const float* __restrict__ bias2,
    float* __restrict__ C, int N)
{
    extern __shared__ __align__(16) uint8_t gsm[];
    uint32_t sA = smem_u32(gsm);
    uint32_t sB = sA + 3 * 128 * GP * 2;
    const int tid = threadIdx.x, w = tid >> 5, lane = tid & 31;
    const int m0 = blockIdx.y * 128, n0 = blockIdx.x * 128;
    const int wr = w >> 1, wc = w & 1;
    const int mw = wr * 64, nw = wc * 64;
    const int g = lane >> 3, r = lane & 7;
    const int tq = lane >> 2, tr = lane & 3;

    float acc[4][8][4];
#pragma unroll
    for (int a = 0; a < 4; a++)
#pragma unroll
        for (int b = 0; b < 8; b++)
#pragma unroll
            for (int c = 0; c < 4; c++) acc[a][b][c] = 0.f;

#define GLOAD(s, kt) do { \
    const uint16_t* PA = ((kt) < 2048) ? Ahi : Alo; \
    const uint16_t* PB = ((kt) < 1024 || (kt) >= 2048) ? Bhi : Blo; \
    int ka = ((kt) < 2048) ? ((kt) & 1023) : ((kt) - 2048); \
    int kb = (kt) & 1023; \
    _Pragma("unroll") \
    for (int t = 0; t < 16; t++) { \
        int j = tid + t * 128; int row = j >> 3, cc = (j & 7) * 8; \
        if (row < 128) \
            cp16(sA + (uint32_t)(((s) * 128 + row) * GP + cc) * 2, PA + (size_t)(m0 + row) * 1024 + ka + cc); \
        else \
            cp16(sB + (uint32_t)(((s) * 128 + row - 128) * GP + cc) * 2, PB + (size_t)(n0 + row - 128) * 1024 + kb + cc); \
    } } while (0)

    const int NK = KE / 64;   // 48
    GLOAD(0, 0); CP_COMMIT();
    GLOAD(1, 64); CP_COMMIT();

    for (int it = 0; it < NK; it++) {
        int s = it % 3;
        if (it == NK - 1) CP_WAIT0(); else CP_WAIT1();
        __syncthreads();
        if (it + 2 < NK) { GLOAD((it + 2) % 3, (it + 2) * 64); CP_COMMIT(); }
        uint32_t baseA = sA + (uint32_t)(s * 128 * GP) * 2;
        uint32_t baseB = sB + (uint32_t)(s * 128 * GP) * 2;
#pragma unroll
        for (int ks = 0; ks < 4; ks++) {
            uint32_t af[4][4];
#pragma unroll
            for (int mi = 0; mi < 4; mi++)
                ldm4(af[mi][0], af[mi][1], af[mi][2], af[mi][3],
                     baseA + (uint32_t)((mw + mi * 16 + r + (g & 1) * 8) * GP + ks * 16 + (g >> 1) * 8) * 2);
#pragma unroll
            for (int nj = 0; nj < 4; nj++) {
                uint32_t b0, b1, b2, b3;
                ldm4(b0, b1, b2, b3,
                     baseB + (uint32_t)((nw + nj * 16 + (g >> 1) * 8 + r) * GP + ks * 16 + (g & 1) * 8) * 2);
#pragma unroll
                for (int mi = 0; mi < 4; mi++) {
                    mma16816(acc[mi][nj * 2 + 0], af[mi][0], af[mi][1], af[mi][2], af[mi][3], b0, b1);
                    mma16816(acc[mi][nj * 2 + 1], af[mi][0], af[mi][1], af[mi][2], af[mi][3], b2, b3);
                }
            }
        }
    }
#undef GLOAD

#pragma unroll
    for (int mi = 0; mi < 4; mi++) {
#pragma unroll
        for (int nt = 0; nt < 8; nt++) {
            int colg = n0 + nw + nt * 8 + tr * 2;
            float b0, b1;
            if (MODE == 0) {
                b0 = (colg < CC) ? bias1[colg] : ((colg < 2 * CC) ? 0.f : bias2[colg - 2 * CC]);
                int c1 = colg + 1;
                b1 = (c1 < CC) ? bias1[c1] : ((c1 < 2 * CC) ? 0.f : bias2[c1 - 2 * CC]);
            } else { b0 = bias1[colg]; b1 = bias1[colg + 1]; }
            int rA = m0 + mw + mi * 16 + tq;
            float2 v0, v1;
            v0.x = acc[mi][nt][0] + b0; v0.y = acc[mi][nt][1] + b1;
            v1.x = acc[mi][nt][2] + b0; v1.y = acc[mi][nt][3] + b1;
            *(float2*)(C + (size_t)rA * N + colg) = v0;
            *(float2*)(C + (size_t)(rA + 8) * N + colg) = v1;
        }
    }
}

// ---------------- normalize + split q,k -> (B,H,L,[hi64|lo64]) ----------------
__global__ __launch_bounds__(256) void norm_split_kernel(const float* __restrict__ scale_mul)
{
    int gwarp = (blockIdx.x * 256 + threadIdx.x) >> 5;
    int lane = threadIdx.x & 31;
    if (gwarp >= BB * LL * HH) return;
    int b = gwarp / (LL * HH), rem = gwarp % (LL * HH);
    int l = rem / HH, h = rem % HH;
    size_t src = (size_t)(b * LL + l) * (3 * CC) + h * DD;
    size_t dst = ((size_t)((b * HH + h) * LL) + l) * 128;
    float sm = __expf(fminf(scale_mul[h], MAX_SM));

    {
        float v0 = g_qkv[src + lane], v1 = g_qkv[src + 32 + lane];
        float ss = v0 * v0 + v1 * v1;
#pragma unroll
        for (int off = 16; off > 0; off >>= 1) ss += __shfl_xor_sync(0xffffffffu, ss, off);
        float inv = sm / fmaxf(sqrtf(ss), 1e-12f);
        uint32_t h0, l0, h1, l1;
        split2(v0 * inv, 0.f, h0, l0);
        split2(v1 * inv, 0.f, h1, l1);
        g_q2[dst + lane] = (uint16_t)h0;      g_q2[dst + 32 + lane] = (uint16_t)h1;
        g_q2[dst + 64 + lane] = (uint16_t)l0; g_q2[dst + 96 + lane] = (uint16_t)l1;
    }
    {
        float v0 = g_qkv[src + CC + lane], v1 = g_qkv[src + CC + 32 + lane];
        float ss = v0 * v0 + v1 * v1;
#pragma unroll
        for (int off = 16; off > 0; off >>= 1) ss += __shfl_xor_sync(0xffffffffu, ss, off);
        float inv = 1.0f / fmaxf(sqrtf(ss), 1e-12f);
        uint32_t h0, l0, h1, l1;
        split2(v0 * inv, 0.f, h0, l0);
        split2(v1 * inv, 0.f, h1, l1);
        g_k2[dst + lane] = (uint16_t)h0;      g_k2[dst + 32 + lane] = (uint16_t)h1;
        g_k2[dst + 64 + lane] = (uint16_t)l0; g_k2[dst + 96 + lane] = (uint16_t)l1;
    }
}

// ---------------- V transpose ----------------
__global__ __launch_bounds__(256) void vtrans_kernel()
{
    __shared__ float vt[64][65];
    int tid = threadIdx.x, c = blockIdx.x, bh = blockIdx.y;
    int b = bh >> 4, h = bh & 15;
    int rr = tid >> 2, cs = (tid & 3) * 16;
    const float* src = g_qkv + (size_t)(b * LL + c * 64 + rr) * (3 * CC) + 2 * CC + h * DD + cs;
#pragma unroll
    for (int j4 = 0; j4 < 4; j4++) {
        float4 v = *(const float4*)(src + j4 * 4);
        vt[cs + j4 * 4 + 0][rr] = v.x; vt[cs + j4 * 4 + 1][rr] = v.y;
        vt[cs + j4 * 4 + 2][rr] = v.z; vt[cs + j4 * 4 + 3][rr] = v.w;
    }
    __syncthreads();
    int d = tid >> 2, js = (tid & 3) * 16;
    uint32_t ho[8], lo[8];
#pragma unroll
    for (int j2 = 0; j2 < 8; j2++)
        split2(vt[d][js + j2 * 2], vt[d][js + j2 * 2 + 1], ho[j2], lo[j2]);
    size_t base = ((size_t)(bh * DD + d)) * (2 * LL) + (size_t)c * 128 + js;
    *(uint4*)(g_vt2 + base)      = *(uint4*)(ho);
    *(uint4*)(g_vt2 + base + 8)  = *(uint4*)(ho + 4);
    *(uint4*)(g_vt2 + base + 64) = *(uint4*)(lo);
    *(uint4*)(g_vt2 + base + 72) = *(uint4*)(lo + 4);
}

// ---------------- flash attention: 64-row Q tiles, Q fragments in registers ----------------
#define FP2 136
#define FQ_OFF 0u
#define FPS_OFF 17408u
#define FK_OFF 34816u
#define FV_OFF 69632u
#define FLR_OFF 104448u
#define FLASH_SMEM 104960
#define KVSTG 17408u

__global__ __launch_bounds__(256, 2) void flash_mma(
    const float* __restrict__ attn_bias, const float* __restrict__ scale_mul)
{
    extern __shared__ __align__(16) uint8_t fsm[];
    uint32_t sb = smem_u32(fsm);
    const int tid = threadIdx.x, w = tid >> 5, lane = tid & 31;
    const int wr = w >> 1, wc = w & 1;
    const int g = lane >> 3, r = lane & 7;
    const int tq = lane >> 2, tr = lane & 3;
    const int q0 = blockIdx.x * 64;
    const int bh = blockIdx.y, b = bh >> 4, h = bh & 15;

    const uint16_t* Qg = g_q2 + ((size_t)bh * LL + q0) * 128;
    const uint16_t* Kg = g_k2 + ((size_t)bh * LL) * 128;
    const uint16_t* Vg = g_vt2 + (size_t)bh * DD * (2 * LL);

    // Q load: own commit group
#pragma unroll
    for (int t = 0; t < 4; t++) {
        int j = tid + t * 256; int row = j >> 4, cc = (j & 15) * 8;
        cp16(sb + FQ_OFF + (uint32_t)(row * FP2 + cc) * 2, Qg + (size_t)row * 128 + cc);
    }
    CP_COMMIT();
#define LOADKV(cidx, s) do { \
    _Pragma("unroll") \
    for (int t = 0; t < 4; t++) { \
        int j = tid + t * 256; int row = j >> 4, cc = (j & 15) * 8; \
        cp16(sb + FK_OFF + (s) * KVSTG + (uint32_t)(row * FP2 + cc) * 2, Kg + (size_t)((cidx) * 64 + row) * 128 + cc); \
        cp16(sb + FV_OFF + (s) * KVSTG + (uint32_t)(row * FP2 + cc) * 2, Vg + (size_t)row * (2 * LL) + (size_t)(cidx) * 128 + cc); \
    } } while (0)

    LOADKV(0, 0); CP_COMMIT();

    // wait for Q only (KV0 group still in flight), then hoist Q fragments to registers
    CP_WAIT1();
    __syncthreads();
    uint32_t qf[2][4][4];   // [sub hi/lo][ks][frag]
#pragma unroll
    for (int sub = 0; sub < 2; sub++)
#pragma unroll
        for (int ks = 0; ks < 4; ks++)
            ldm4(qf[sub][ks][0], qf[sub][ks][1], qf[sub][ks][2], qf[sub][ks][3],
                 sb + FQ_OFF + (uint32_t)((wr * 16 + r + (g & 1) * 8) * FP2 + sub * 64 + ks * 16 + (g >> 1) * 8) * 2);

    const float M = __expf(fminf(scale_mul[h], MAX_SM)) + __uint_as_float(g_bmax_bits);
    float oacc[4][4];
    float lsum[2] = {0.f, 0.f};
#pragma unroll
    for (int n = 0; n < 4; n++)
#pragma unroll
        for (int e = 0; e < 4; e++) oacc[n][e] = 0.f;

    const int QSEL[3] = {0, 0, 1}, SUBB[3] = {0, 64, 0};

    for (int c = 0; c < 32; c++) {
        int s = c & 1;
        CP_WAIT0();
        __syncthreads();
        if (c < 31) { LOADKV(c + 1, s ^ 1); CP_COMMIT(); }

        int ktg = c * 64;
        float2 bb[4][2];
        {
            int rA = wr * 16 + tq;
#pragma unroll
            for (int nt = 0; nt < 4; nt++) {
                int cl = wc * 32 + nt * 8 + tr * 2;
                bb[nt][0] = *(const float2*)(attn_bias + (size_t)(q0 + rA) * LL + ktg + cl);
                bb[nt][1] = *(const float2*)(attn_bias + (size_t)(q0 + rA + 8) * LL + ktg + cl);
            }
        }

        float sacc[4][4];
#pragma unroll
        for (int n = 0; n < 4; n++)
#pragma unroll
            for (int e = 0; e < 4; e++) sacc[n][e] = 0.f;

        uint32_t bK = sb + FK_OFF + s * KVSTG;
#pragma unroll
        for (int p = 0; p < 3; p++) {
            int qs = QSEL[p], bsub = SUBB[p];
#pragma unroll
            for (int ks = 0; ks < 4; ks++) {
#pragma unroll
                for (int nj = 0; nj < 2; nj++) {
                    uint32_t b0, b1, b2, b3;
                    ldm4(b0, b1, b2, b3,
                         bK + (uint32_t)((wc * 32 + nj * 16 + (g >> 1) * 8 + r) * FP2 + bsub + ks * 16 + (g & 1) * 8) * 2);
                    mma16816(sacc[nj * 2 + 0], qf[qs][ks][0], qf[qs][ks][1], qf[qs][ks][2], qf[qs][ks][3], b0, b1);
                    mma16816(sacc[nj * 2 + 1], qf[qs][ks][0], qf[qs][ks][1], qf[qs][ks][2], qf[qs][ks][3], b2, b3);
                }
            }
        }

        {
            int rA = wr * 16 + tq;
#pragma unroll
            for (int nt = 0; nt < 4; nt++) {
                int cl = wc * 32 + nt * 8 + tr * 2;
                float p00 = __expf(sacc[nt][0] + bb[nt][0].x - M);
                float p01 = __expf(sacc[nt][1] + bb[nt][0].y - M);
                float p10 = __expf(sacc[nt][2] + bb[nt][1].x - M);
                float p11 = __expf(sacc[nt][3] + bb[nt][1].y - M);
                lsum[0] += p00 + p01;
                lsum[1] += p10 + p11;
                uint32_t hA, lA, hB, lB;
                split2(p00, p01, hA, lA);
                split2(p10, p11, hB, lB);
                uint32_t a0 = sb + FPS_OFF + (uint32_t)(rA * FP2 + cl) * 2;
                uint32_t a1 = sb + FPS_OFF + (uint32_t)((rA + 8) * FP2 + cl) * 2;
                st32s(a0, hA); st32s(a0 + 128, lA);
                st32s(a1, hB); st32s(a1 + 128, lB);
            }
        }
        __syncthreads();

        uint32_t bV = sb + FV_OFF + s * KVSTG;
#pragma unroll
        for (int p = 0; p < 3; p++) {
            int asub = (p == 2) ? 64 : 0, bsub = SUBB[p];
#pragma unroll
            for (int ks = 0; ks < 4; ks++) {
                uint32_t a0, a1, a2, a3;
                ldm4(a0, a1, a2, a3,
                     sb + FPS_OFF + (uint32_t)((wr * 16 + r + (g & 1) * 8) * FP2 + asub + ks * 16 + (g >> 1) * 8) * 2);
#pragma unroll
                for (int nj = 0; nj < 2; nj++) {
                    uint32_t b0, b1, b2, b3;
                    ldm4(b0, b1, b2, b3,
                         bV + (uint32_t)((wc * 32 + nj * 16 + (g >> 1) * 8 + r) * FP2 + bsub + ks * 16 + (g & 1) * 8) * 2);
                    mma16816(oacc[nj * 2 + 0], a0, a1, a2, a3, b0, b1);
                    mma16816(oacc[nj * 2 + 1], a0, a1, a2, a3, b2, b3);
                }
            }
        }
        // next chunk's top sync orders PV reads before overwrites
    }
#undef LOADKV

#pragma unroll
    for (int a = 0; a < 2; a++) {
        lsum[a] += __shfl_xor_sync(0xffffffffu, lsum[a], 1);
        lsum[a] += __shfl_xor_sync(0xffffffffu, lsum[a], 2);
    }
    float* lred = (float*)(fsm + FLR_OFF);
    __syncthreads();
    if (tr == 0) {
        lred[(wr * 16 + tq) * 2 + wc] = lsum[0];
        lred[(wr * 16 + tq + 8) * 2 + wc] = lsum[1];
    }
    __syncthreads();
    {
        int rA = wr * 16 + tq;
        float inv0 = 1.f / (lred[rA * 2] + lred[rA * 2 + 1]);
        float inv1 = 1.f / (lred[(rA + 8) * 2] + lred[(rA + 8) * 2 + 1]);
        size_t r0g = (size_t)(b * LL + q0 + rA) * CC + h * DD;
        size_t r1g = (size_t)(b * LL + q0 + rA + 8) * CC + h * DD;
#pragma unroll
        for (int nt = 0; nt < 4; nt++) {
            int cl = wc * 32 + nt * 8 + tr * 2;
            uint32_t hA, lA, hB, lB;
            split2(oacc[nt][0] * inv0, oacc[nt][1] * inv0, hA, lA);
            split2(oacc[nt][2] * inv1, oacc[nt][3] * inv1, hB, lB);
            *(uint32_t*)(g_ah + r0g + cl) = hA;
            *(uint32_t*)(g_al + r0g + cl) = lA;
            *(uint32_t*)(g_ah + r1g + cl) = hB;
            *(uint32_t*)(g_al + r1g + cl) = lB;
        }
    }
}

extern "C" void kernel_launch(void* const* d_in, const int* in_sizes, int n_in,
                              void* d_out, int out_size)
{
    const float* x         = (const float*)d_in[0];
    const float* attn_bias = (const float*)d_in[1];
    const float* W_qkv     = (const float*)d_in[2];
    const float* q_bias    = (const float*)d_in[3];
    const float* v_bias    = (const float*)d_in[4];
    const float* scale_mul = (const float*)d_in[5];
    const float* W_proj    = (const float*)d_in[6];
    const float* b_proj    = (const float*)d_in[7];
    float* out = (float*)d_out;

    float* qkv_p;
    uint16_t *xh, *xl, *wqh, *wql, *wph, *wpl, *ah, *al;
    cudaGetSymbolAddress((void**)&qkv_p, g_qkv);
    cudaGetSymbolAddress((void**)&xh, g_xh);   cudaGetSymbolAddress((void**)&xl, g_xl);
    cudaGetSymbolAddress((void**)&wqh, g_wqh); cudaGetSymbolAddress((void**)&wql, g_wql);
    cudaGetSymbolAddress((void**)&wph, g_wph); cudaGetSymbolAddress((void**)&wpl, g_wpl);
    cudaGetSymbolAddress((void**)&ah, g_ah);   cudaGetSymbolAddress((void**)&al, g_al);

    cudaFuncSetAttribute(gemm_bf16<0>, cudaFuncAttributeMaxDynamicSharedMemorySize, GEMM_SMEM);
    cudaFuncSetAttribute(gemm_bf16<1>, cudaFuncAttributeMaxDynamicSharedMemorySize, GEMM_SMEM);
    cudaFuncSetAttribute(flash_mma, cudaFuncAttributeMaxDynamicSharedMemorySize, FLASH_SMEM);

    split_kernel<<<(MM * CC / 4 + 255) / 256, 256>>>(x, xh, xl, MM * CC / 4);
    split_kernel<<<(3 * CC * CC / 4 + 255) / 256, 256>>>(W_qkv, wqh, wql, 3 * CC * CC / 4);
    split_kernel<<<(CC * CC / 4 + 255) / 256, 256>>>(W_proj, wph, wpl, CC * CC / 4);

    gemm_bf16<0><<<dim3(3 * CC / 128, MM / 128), 128, GEMM_SMEM>>>(
        xh, xl, wqh, wql, q_bias, v_bias, qkv_p, 3 * CC);

    bmax_reduce<<<512, 256>>>(attn_bias, LL * LL / 4);
    norm_split_kernel<<<(BB * LL * HH * 32) / 256, 256>>>(scale_mul);
    vtrans_kernel<<<dim3(LL / 64, BB * HH), 256>>>();

    flash_mma<<<dim3(LL / 64, BB * HH), 256, FLASH_SMEM>>>(attn_bias, scale_mul);

    gemm_bf16<1><<<dim3(CC / 128, MM / 128), 128, GEMM_SMEM>>>(
        ah, al, wph, wpl, b_proj, nullptr, out, CC);
}

// round 10
// speedup vs baseline: 2.7510x; 1.0704x over previous
#include <cuda_runtime.h>
#include <math.h>
#include <stdint.h>

#define BB 2
#define LL 2048
#define CC 1024
#define HH 16
#define DD 64
#define MM (BB * LL)
#define KE 3072
#define MAX_SM 4.6051701859880913680f

__device__ float    g_qkv[MM * 3 * CC];
__device__ uint16_t g_xh[MM * CC],  g_xl[MM * CC];
__device__ uint16_t g_wqh[3 * CC * CC], g_wql[3 * CC * CC];
__device__ uint16_t g_wph[CC * CC], g_wpl[CC * CC];
__device__ uint16_t g_q2[BB * HH * LL * 128];
__device__ uint16_t g_k2[BB * HH * LL * 128];
__device__ uint16_t g_vt2[(size_t)BB * HH * DD * 2 * LL];
__device__ uint16_t g_ah[MM * CC], g_al[MM * CC];
__device__ unsigned g_bmax_bits;   // zero at load; atomicMax idempotent per replay

__device__ __forceinline__ uint32_t smem_u32(const void* p) {
    uint32_t a;
    asm("{ .reg .u64 t; cvta.to.shared.u64 t, %1; cvt.u32.u64 %0, t; }" : "=r"(a) : "l"(p));
    return a;
}
__device__ __forceinline__ void cp16(uint32_t dst, const void* src) {
    asm volatile("cp.async.cg.shared.global [%0], [%1], 16;" :: "r"(dst), "l"(src));
}
#define CP_COMMIT() asm volatile("cp.async.commit_group;")
#define CP_WAIT0()  asm volatile("cp.async.wait_group 0;" ::: "memory")
#define CP_WAIT1()  asm volatile("cp.async.wait_group 1;" ::: "memory")

__device__ __forceinline__ void ldm4(uint32_t& r0, uint32_t& r1, uint32_t& r2, uint32_t& r3, uint32_t a) {
    asm volatile("ldmatrix.sync.aligned.m8n8.x4.shared.b16 {%0,%1,%2,%3}, [%4];"
                 : "=r"(r0), "=r"(r1), "=r"(r2), "=r"(r3) : "r"(a));
}
__device__ __forceinline__ void mma16816(float* c, uint32_t a0, uint32_t a1, uint32_t a2, uint32_t a3,
                                         uint32_t b0, uint32_t b1) {
    asm volatile("mma.sync.aligned.m16n8k16.row.col.f32.bf16.bf16.f32 "
                 "{%0,%1,%2,%3}, {%4,%5,%6,%7}, {%8,%9}, {%0,%1,%2,%3};"
                 : "+f"(c[0]), "+f"(c[1]), "+f"(c[2]), "+f"(c[3])
                 : "r"(a0), "r"(a1), "r"(a2), "r"(a3), "r"(b0), "r"(b1));
}
__device__ __forceinline__ uint32_t pack_bf(float lo, float hi) {
    uint32_t r;
    asm("cvt.rn.bf16x2.f32 %0, %1, %2;" : "=r"(r) : "f"(hi), "f"(lo));
    return r;
}
__device__ __forceinline__ void split2(float a, float b, uint32_t& hi, uint32_t& lo) {
    hi = pack_bf(a, b);
    float ha = __uint_as_float(hi << 16);
    float hb = __uint_as_float(hi & 0xFFFF0000u);
    lo = pack_bf(a - ha, b - hb);
}

__global__ __launch_bounds__(256) void split_kernel(
    const float* __restrict__ in, uint16_t* __restrict__ hi,
    uint16_t* __restrict__ lo, int n4)
{
    int i = blockIdx.x * 256 + threadIdx.x;
    if (i >= n4) return;
    float4 v = ((const float4*)in)[i];
    uint32_t h01, l01, h23, l23;
    split2(v.x, v.y, h01, l01);
    split2(v.z, v.w, h23, l23);
    uint2 hv; hv.x = h01; hv.y = h23;
    uint2 lv; lv.x = l01; lv.y = l23;
    ((uint2*)hi)[i] = hv;
    ((uint2*)lo)[i] = lv;
}

__global__ __launch_bounds__(256) void bmax_reduce(const float* __restrict__ b, int n4)
{
    float m = 0.f;
    for (int i = blockIdx.x * 256 + threadIdx.x; i < n4; i += gridDim.x * 256) {
        float4 v = ((const float4*)b)[i];
        m = fmaxf(m, fmaxf(fmaxf(fabsf(v.x), fabsf(v.y)), fmaxf(fabsf(v.z), fabsf(v.w))));
    }
#pragma unroll
    for (int off = 16; off > 0; off >>= 1)
        m = fmaxf(m, __shfl_xor_sync(0xffffffffu, m, off));
    if ((threadIdx.x & 31) == 0) atomicMax(&g_bmax_bits, __float_as_uint(m));
}

// ---------------- GEMM (R8 config): BK=64, 2-stage, 3 CTAs/SM ----------------
#define GP 72
#define GEMM_SMEM (2 * 256 * GP * 2)

template <int MODE>
__global__ __launch_bounds__(128, 3) void gemm_bf16(
    const uint16_t* __restrict__ Ahi, const uint16_t* __restrict__ Alo,
    const uint16_t* __restrict__ Bhi, const uint16_t* __restrict__ Blo,
    const float* __restrict__ bias1, const float* __restrict__ bias2,
    float* __restrict__ C, int N)
{
    extern __shared__ __align__(16) uint8_t gsm[];
    uint32_t sA = smem_u32(gsm);
    uint32_t sB = sA + 2 * 128 * GP * 2;
    const int tid = threadIdx.x, w = tid >> 5, lane = tid & 31;
    const int m0 = blockIdx.y * 128, n0 = blockIdx.x * 128;
    const int wr = w >> 1, wc = w & 1;
    const int mw = wr * 64, nw = wc * 64;
    const int g = lane >> 3, r = lane & 7;
    const int tq = lane >> 2, tr = lane & 3;

    float acc[4][8][4];
#pragma unroll
    for (int a = 0; a < 4; a++)
#pragma unroll
        for (int b = 0; b < 8; b++)
#pragma unroll
            for (int c = 0; c < 4; c++) acc[a][b][c] = 0.f;

#define GLOAD(s, kt) do { \
    const uint16_t* PA = ((kt) < 2048) ? Ahi : Alo; \
    const uint16_t* PB = ((kt) < 1024 || (kt) >= 2048) ? Bhi : Blo; \
    int ka = ((kt) < 2048) ? ((kt) & 1023) : ((kt) - 2048); \
    int kb = (kt) & 1023; \
    _Pragma("unroll") \
    for (int t = 0; t < 16; t++) { \
        int j = tid + t * 128; int row = j >> 3, cc = (j & 7) * 8; \
        if (row < 128) \
            cp16(sA + (uint32_t)(((s) * 128 + row) * GP + cc) * 2, PA + (size_t)(m0 + row) * 1024 + ka + cc); \
        else \
            cp16(sB + (uint32_t)(((s) * 128 + row - 128) * GP + cc) * 2, PB + (size_t)(n0 + row - 128) * 1024 + kb + cc); \
    } } while (0)

    const int NK = KE / 64;   // 48
    GLOAD(0, 0); CP_COMMIT();

    for (int it = 0; it < NK; it++) {
        int s = it & 1;
        CP_WAIT0();
        __syncthreads();
        if (it + 1 < NK) { GLOAD(s ^ 1, (it + 1) * 64); CP_COMMIT(); }
        uint32_t baseA = sA + (uint32_t)(s * 128 * GP) * 2;
        uint32_t baseB = sB + (uint32_t)(s * 128 * GP) * 2;
#pragma unroll
        for (int ks = 0; ks < 4; ks++) {
            uint32_t af[4][4];
#pragma unroll
            for (int mi = 0; mi < 4; mi++)
                ldm4(af[mi][0], af[mi][1], af[mi][2], af[mi][3],
                     baseA + (uint32_t)((mw + mi * 16 + r + (g & 1) * 8) * GP + ks * 16 + (g >> 1) * 8) * 2);
#pragma unroll
            for (int nj = 0; nj < 4; nj++) {
                uint32_t b0, b1, b2, b3;
                ldm4(b0, b1, b2, b3,
                     baseB + (uint32_t)((nw + nj * 16 + (g >> 1) * 8 + r) * GP + ks * 16 + (g & 1) * 8) * 2);
#pragma unroll
                for (int mi = 0; mi < 4; mi++) {
                    mma16816(acc[mi][nj * 2 + 0], af[mi][0], af[mi][1], af[mi][2], af[mi][3], b0, b1);
                    mma16816(acc[mi][nj * 2 + 1], af[mi][0], af[mi][1], af[mi][2], af[mi][3], b2, b3);
                }
            }
        }
    }
#undef GLOAD

#pragma unroll
    for (int mi = 0; mi < 4; mi++) {
#pragma unroll
        for (int nt = 0; nt < 8; nt++) {
            int colg = n0 + nw + nt * 8 + tr * 2;
            float b0, b1;
            if (MODE == 0) {
                b0 = (colg < CC) ? bias1[colg] : ((colg < 2 * CC) ? 0.f : bias2[colg - 2 * CC]);
                int c1 = colg + 1;
                b1 = (c1 < CC) ? bias1[c1] : ((c1 < 2 * CC) ? 0.f : bias2[c1 - 2 * CC]);
            } else { b0 = bias1[colg]; b1 = bias1[colg + 1]; }
            int rA = m0 + mw + mi * 16 + tq;
            float2 v0, v1;
            v0.x = acc[mi][nt][0] + b0; v0.y = acc[mi][nt][1] + b1;
            v1.x = acc[mi][nt][2] + b0; v1.y = acc[mi][nt][3] + b1;
            *(float2*)(C + (size_t)rA * N + colg) = v0;
            *(float2*)(C + (size_t)(rA + 8) * N + colg) = v1;
        }
    }
}

// ---------------- normalize + split q,k ----------------
__global__ __launch_bounds__(256) void norm_split_kernel(const float* __restrict__ scale_mul)
{
    int gwarp = (blockIdx.x * 256 + threadIdx.x) >> 5;
    int lane = threadIdx.x & 31;
    if (gwarp >= BB * LL * HH) return;
    int b = gwarp / (LL * HH), rem = gwarp % (LL * HH);
    int l = rem / HH, h = rem % HH;
    size_t src = (size_t)(b * LL + l) * (3 * CC) + h * DD;
    size_t dst = ((size_t)((b * HH + h) * LL) + l) * 128;
    float sm = __expf(fminf(scale_mul[h], MAX_SM));

    {
        float v0 = g_qkv[src + lane], v1 = g_qkv[src + 32 + lane];
        float ss = v0 * v0 + v1 * v1;
#pragma unroll
        for (int off = 16; off > 0; off >>= 1) ss += __shfl_xor_sync(0xffffffffu, ss, off);
        float inv = sm / fmaxf(sqrtf(ss), 1e-12f);
        uint32_t h0, l0, h1, l1;
        split2(v0 * inv, 0.f, h0, l0);
        split2(v1 * inv, 0.f, h1, l1);
        g_q2[dst + lane] = (uint16_t)h0;      g_q2[dst + 32 + lane] = (uint16_t)h1;
        g_q2[dst + 64 + lane] = (uint16_t)l0; g_q2[dst + 96 + lane] = (uint16_t)l1;
    }
    {
        float v0 = g_qkv[src + CC + lane], v1 = g_qkv[src + CC + 32 + lane];
        float ss = v0 * v0 + v1 * v1;
#pragma unroll
        for (int off = 16; off > 0; off >>= 1) ss += __shfl_xor_sync(0xffffffffu, ss, off);
        float inv = 1.0f / fmaxf(sqrtf(ss), 1e-12f);
        uint32_t h0, l0, h1, l1;
        split2(v0 * inv, 0.f, h0, l0);
        split2(v1 * inv, 0.f, h1, l1);
        g_k2[dst + lane] = (uint16_t)h0;      g_k2[dst + 32 + lane] = (uint16_t)h1;
        g_k2[dst + 64 + lane] = (uint16_t)l0; g_k2[dst + 96 + lane] = (uint16_t)l1;
    }
}

// ---------------- V transpose ----------------
__global__ __launch_bounds__(256) void vtrans_kernel()
{
    __shared__ float vt[64][65];
    int tid = threadIdx.x, c = blockIdx.x, bh = blockIdx.y;
    int b = bh >> 4, h = bh & 15;
    int rr = tid >> 2, cs = (tid & 3) * 16;
    const float* src = g_qkv + (size_t)(b * LL + c * 64 + rr) * (3 * CC) + 2 * CC + h * DD + cs;
#pragma unroll
    for (int j4 = 0; j4 < 4; j4++) {
        float4 v = *(const float4*)(src + j4 * 4);
        vt[cs + j4 * 4 + 0][rr] = v.x; vt[cs + j4 * 4 + 1][rr] = v.y;
        vt[cs + j4 * 4 + 2][rr] = v.z; vt[cs + j4 * 4 + 3][rr] = v.w;
    }
    __syncthreads();
    int d = tid >> 2, js = (tid & 3) * 16;
    uint32_t ho[8], lo[8];
#pragma unroll
    for (int j2 = 0; j2 < 8; j2++)
        split2(vt[d][js + j2 * 2], vt[d][js + j2 * 2 + 1], ho[j2], lo[j2]);
    size_t base = ((size_t)(bh * DD + d)) * (2 * LL) + (size_t)c * 128 + js;
    *(uint4*)(g_vt2 + base)      = *(uint4*)(ho);
    *(uint4*)(g_vt2 + base + 8)  = *(uint4*)(ho + 4);
    *(uint4*)(g_vt2 + base + 64) = *(uint4*)(lo);
    *(uint4*)(g_vt2 + base + 72) = *(uint4*)(lo + 4);
}

// ---------------- flash: Q + P in registers; per-warp k-split PV; O exchange at end ----------------
#define FP2 136
#define FQ_OFF 0u            // 17408B: Q tiles, then reused as O-exchange (64 x 68 fp32)
#define FK_OFF 17408u
#define FV_OFF 52224u
#define FLR_OFF 87040u
#define FLASH_SMEM 87808
#define KVSTG 17408u
#define OEP 68

__global__ __launch_bounds__(256, 2) void flash_mma(
    const float* __restrict__ attn_bias, const float* __restrict__ scale_mul)
{
    extern __shared__ __align__(16) uint8_t fsm[];
    uint32_t sb = smem_u32(fsm);
    const int tid = threadIdx.x, w = tid >> 5, lane = tid & 31;
    const int wr = w >> 1, wc = w & 1;
    const int g = lane >> 3, r = lane & 7;
    const int tq = lane >> 2, tr = lane & 3;
    const int q0 = blockIdx.x * 64;
    const int bh = blockIdx.y, b = bh >> 4, h = bh & 15;

    const uint16_t* Qg = g_q2 + ((size_t)bh * LL + q0) * 128;
    const uint16_t* Kg = g_k2 + ((size_t)bh * LL) * 128;
    const uint16_t* Vg = g_vt2 + (size_t)bh * DD * (2 * LL);

#pragma unroll
    for (int t = 0; t < 4; t++) {
        int j = tid + t * 256; int row = j >> 4, cc = (j & 15) * 8;
        cp16(sb + FQ_OFF + (uint32_t)(row * FP2 + cc) * 2, Qg + (size_t)row * 128 + cc);
    }
    CP_COMMIT();
#define LOADKV(cidx, s) do { \
    _Pragma("unroll") \
    for (int t = 0; t < 4; t++) { \
        int j = tid + t * 256; int row = j >> 4, cc = (j & 15) * 8; \
        cp16(sb + FK_OFF + (s) * KVSTG + (uint32_t)(row * FP2 + cc) * 2, Kg + (size_t)((cidx) * 64 + row) * 128 + cc); \
        cp16(sb + FV_OFF + (s) * KVSTG + (uint32_t)(row * FP2 + cc) * 2, Vg + (size_t)row * (2 * LL) + (size_t)(cidx) * 128 + cc); \
    } } while (0)

    LOADKV(0, 0); CP_COMMIT();

    // wait for Q only; hoist Q fragments
    CP_WAIT1();
    __syncthreads();
    uint32_t qf[2][4][4];
#pragma unroll
    for (int sub = 0; sub < 2; sub++)
#pragma unroll
        for (int ks = 0; ks < 4; ks++)
            ldm4(qf[sub][ks][0], qf[sub][ks][1], qf[sub][ks][2], qf[sub][ks][3],
                 sb + FQ_OFF + (uint32_t)((wr * 16 + r + (g & 1) * 8) * FP2 + sub * 64 + ks * 16 + (g >> 1) * 8) * 2);

    const float M = __expf(fminf(scale_mul[h], MAX_SM)) + __uint_as_float(g_bmax_bits);
    float oacc[8][4];
    float lsum[2] = {0.f, 0.f};
#pragma unroll
    for (int n = 0; n < 8; n++)
#pragma unroll
        for (int e = 0; e < 4; e++) oacc[n][e] = 0.f;

    const int QSEL[3] = {0, 0, 1}, SUBB[3] = {0, 64, 0};

    for (int c = 0; c < 32; c++) {
        int s = c & 1;
        CP_WAIT0();
        __syncthreads();
        if (c < 31) { LOADKV(c + 1, s ^ 1); CP_COMMIT(); }

        int ktg = c * 64;
        float2 bb[4][2];
        {
            int rA = wr * 16 + tq;
#pragma unroll
            for (int nt = 0; nt < 4; nt++) {
                int cl = wc * 32 + nt * 8 + tr * 2;
                bb[nt][0] = *(const float2*)(attn_bias + (size_t)(q0 + rA) * LL + ktg + cl);
                bb[nt][1] = *(const float2*)(attn_bias + (size_t)(q0 + rA + 8) * LL + ktg + cl);
            }
        }

        float sacc[4][4];
#pragma unroll
        for (int n = 0; n < 4; n++)
#pragma unroll
            for (int e = 0; e < 4; e++) sacc[n][e] = 0.f;

        uint32_t bK = sb + FK_OFF + s * KVSTG;
#pragma unroll
        for (int p = 0; p < 3; p++) {
            int qs = QSEL[p], bsub = SUBB[p];
#pragma unroll
            for (int ks = 0; ks < 4; ks++) {
#pragma unroll
                for (int nj = 0; nj < 2; nj++) {
                    uint32_t b0, b1, b2, b3;
                    ldm4(b0, b1, b2, b3,
                         bK + (uint32_t)((wc * 32 + nj * 16 + (g >> 1) * 8 + r) * FP2 + bsub + ks * 16 + (g & 1) * 8) * 2);
                    mma16816(sacc[nj * 2 + 0], qf[qs][ks][0], qf[qs][ks][1], qf[qs][ks][2], qf[qs][ks][3], b0, b1);
                    mma16816(sacc[nj * 2 + 1], qf[qs][ks][0], qf[qs][ks][1], qf[qs][ks][2], qf[qs][ks][3], b2, b3);
                }
            }
        }

        // exp + build P fragments in registers (C-frag == A-frag layout)
        uint32_t pHi[2][4], pLo[2][4];
#pragma unroll
        for (int nt = 0; nt < 4; nt++) {
            float p00 = __expf(sacc[nt][0] + bb[nt][0].x - M);
            float p01 = __expf(sacc[nt][1] + bb[nt][0].y - M);
            float p10 = __expf(sacc[nt][2] + bb[nt][1].x - M);
            float p11 = __expf(sacc[nt][3] + bb[nt][1].y - M);
            lsum[0] += p00 + p01;
            lsum[1] += p10 + p11;
            uint32_t hA, lA, hB, lB;
            split2(p00, p01, hA, lA);
            split2(p10, p11, hB, lB);
            int kk = nt >> 1, e = (nt & 1) * 2;
            pHi[kk][e] = hA; pHi[kk][e + 1] = hB;
            pLo[kk][e] = lA; pLo[kk][e + 1] = lB;
        }

        // PV: A = P regs (own k=32 cols), B = V^T all 64 d cols; O is k-partial
        uint32_t bV = sb + FV_OFF + s * KVSTG;
#pragma unroll
        for (int p = 0; p < 3; p++) {
            int bsub = SUBB[p];
#pragma unroll
            for (int ks = 0; ks < 2; ks++) {
                const uint32_t* A = (p < 2) ? pHi[ks] : pLo[ks];
#pragma unroll
                for (int nj = 0; nj < 4; nj++) {
                    uint32_t b0, b1, b2, b3;
                    ldm4(b0, b1, b2, b3,
                         bV + (uint32_t)((nj * 16 + (g >> 1) * 8 + r) * FP2 + bsub + wc * 32 + ks * 16 + (g & 1) * 8) * 2);
                    mma16816(oacc[nj * 2 + 0], A[0], A[1], A[2], A[3], b0, b1);
                    mma16816(oacc[nj * 2 + 1], A[0], A[1], A[2], A[3], b2, b3);
                }
            }
        }
        // no mid/trailing sync: next chunk's top sync orders smem reuse
    }
#undef LOADKV

    // row-sum reduce across tr lanes + wc warps
#pragma unroll
    for (int a = 0; a < 2; a++) {
        lsum[a] += __shfl_xor_sync(0xffffffffu, lsum[a], 1);
        lsum[a] += __shfl_xor_sync(0xffffffffu, lsum[a], 2);
    }
    float* lred = (float*)(fsm + FLR_OFF);
    float* obuf = (float*)(fsm + FQ_OFF);   // Q region retired; 64 x OEP fp32
    __syncthreads();                        // all warps past last PV (Q frags dead)
    if (tr == 0) {
        lred[(wr * 16 + tq) * 2 + wc] = lsum[0];
        lred[(wr * 16 + tq + 8) * 2 + wc] = lsum[1];
    }
    // wc=1 warps deposit their k-partial O
    if (wc == 1) {
#pragma unroll
        for (int nj = 0; nj < 8; nj++) {
            int cl = nj * 8 + tr * 2;
            *(float2*)&obuf[(wr * 16 + tq) * OEP + cl]     = make_float2(oacc[nj][0], oacc[nj][1]);
            *(float2*)&obuf[(wr * 16 + tq + 8) * OEP + cl] = make_float2(oacc[nj][2], oacc[nj][3]);
        }
    }
    __syncthreads();
    if (wc == 0) {
        int rA = wr * 16 + tq;
        float inv0 = 1.f / (lred[rA * 2] + lred[rA * 2 + 1]);
        float inv1 = 1.f / (lred[(rA + 8) * 2] + lred[(rA + 8) * 2 + 1]);
        size_t r0g = (size_t)(b * LL + q0 + rA) * CC + h * DD;
        size_t r1g = (size_t)(b * LL + q0 + rA + 8) * CC + h * DD;
#pragma unroll
        for (int nj = 0; nj < 8; nj++) {
            int cl = nj * 8 + tr * 2;
            float2 o0 = *(float2*)&obuf[rA * OEP + cl];
            float2 o1 = *(float2*)&obuf[(rA + 8) * OEP + cl];
            uint32_t hA, lA, hB, lB;
            split2((oacc[nj][0] + o0.x) * inv0, (oacc[nj][1] + o0.y) * inv0, hA, lA);
            split2((oacc[nj][2] + o1.x) * inv1, (oacc[nj][3] + o1.y) * inv1, hB, lB);
            *(uint32_t*)(g_ah + r0g + cl) = hA;
            *(uint32_t*)(g_al + r0g + cl) = lA;
            *(uint32_t*)(g_ah + r1g + cl) = hB;
            *(uint32_t*)(g_al + r1g + cl) = lB;
        }
    }
}

extern "C" void kernel_launch(void* const* d_in, const int* in_sizes, int n_in,
                              void* d_out, int out_size)
{
    const float* x         = (const float*)d_in[0];
    const float* attn_bias = (const float*)d_in[1];
    const float* W_qkv     = (const float*)d_in[2];
    const float* q_bias    = (const float*)d_in[3];
    const float* v_bias    = (const float*)d_in[4];
    const float* scale_mul = (const float*)d_in[5];
    const float* W_proj    = (const float*)d_in[6];
    const float* b_proj    = (const float*)d_in[7];
    float* out = (float*)d_out;

    float* qkv_p;
    uint16_t *xh, *xl, *wqh, *wql, *wph, *wpl, *ah, *al;
    cudaGetSymbolAddress((void**)&qkv_p, g_qkv);
    cudaGetSymbolAddress((void**)&xh, g_xh);   cudaGetSymbolAddress((void**)&xl, g_xl);
    cudaGetSymbolAddress((void**)&wqh, g_wqh); cudaGetSymbolAddress((void**)&wql, g_wql);
    cudaGetSymbolAddress((void**)&wph, g_wph); cudaGetSymbolAddress((void**)&wpl, g_wpl);
    cudaGetSymbolAddress((void**)&ah, g_ah);   cudaGetSymbolAddress((void**)&al, g_al);

    cudaFuncSetAttribute(gemm_bf16<0>, cudaFuncAttributeMaxDynamicSharedMemorySize, GEMM_SMEM);
    cudaFuncSetAttribute(gemm_bf16<1>, cudaFuncAttributeMaxDynamicSharedMemorySize, GEMM_SMEM);
    cudaFuncSetAttribute(flash_mma, cudaFuncAttributeMaxDynamicSharedMemorySize, FLASH_SMEM);

    split_kernel<<<(MM * CC / 4 + 255) / 256, 256>>>(x, xh, xl, MM * CC / 4);
    split_kernel<<<(3 * CC * CC / 4 + 255) / 256, 256>>>(W_qkv, wqh, wql, 3 * CC * CC / 4);
    split_kernel<<<(CC * CC / 4 + 255) / 256, 256>>>(W_proj, wph, wpl, CC * CC / 4);

    gemm_bf16<0><<<dim3(3 * CC / 128, MM / 128), 128, GEMM_SMEM>>>(
        xh, xl, wqh, wql, q_bias, v_bias, qkv_p, 3 * CC);

    bmax_reduce<<<512, 256>>>(attn_bias, LL * LL / 4);
    norm_split_kernel<<<(BB * LL * HH * 32) / 256, 256>>>(scale_mul);
    vtrans_kernel<<<dim3(LL / 64, BB * HH), 256>>>();

    flash_mma<<<dim3(LL / 64, BB * HH), 256, FLASH_SMEM>>>(attn_bias, scale_mul);

    gemm_bf16<1><<<dim3(CC / 128, MM / 128), 128, GEMM_SMEM>>>(
        ah, al, wph, wpl, b_proj, nullptr, out, CC);
}